// round 5
// baseline (speedup 1.0000x reference)
#include <cuda_runtime.h>
#include <math.h>

// Problem constants
#define Nn   100000   // num_nodes
#define Hd   128      // hidden_dim
#define Bb   512      // batch (events)
#define Dd   32       // neighbors per event
#define NEGS 5        // negative samples
#define NCTA 19       // 16 neighbor CTAs + h_u CTA + (s,hawkes) CTA + (rec_e) CTA

// ---------------- device scratch (no allocations allowed) ----------------
// float4-typed for guaranteed 16B alignment of vector accesses.
__device__ float4 z_buf4[(size_t)Nn * Hd / 4];   // mutable copy of z0 (51.2 MB)
#define z_buf ((float*)z_buf4)

__device__ float4 g_Wh4[Hd * Hd / 4];     // aligned copies of the weight matrices
__device__ float4 g_We2n4[Hd * Hd / 4];
__device__ float4 g_Wrece4[Hd * Hd / 4];
__device__ float4 g_Wrecn4[Hd * Hd / 4];

__device__ float s_buf[Hd];                // z_u @ W_e2n + b_e2n  (per step)
__device__ float r_buf[Hd];                // z_u @ W_rec_e + b_rec_e (per step)
__device__ unsigned bar_cnt;               // zero-init; returns to 0 each launch
__device__ unsigned bar_gen;               // monotonically grows; sampled at start

// ---------------- helpers ----------------
__device__ __forceinline__ float sigmoidf_(float x) {
    return 1.0f / (1.0f + expf(-x));
}
__device__ __forceinline__ float softplusf_(float x) {
    // stable: max(x,0) + log1p(exp(-|x|))
    return fmaxf(x, 0.0f) + log1pf(expf(-fabsf(x)));
}

// Sense/generation grid barrier across NCTA co-resident CTAs.
__device__ __forceinline__ void grid_barrier(unsigned& gen) {
    __syncthreads();
    if (threadIdx.x == 0) {
        __threadfence();                      // make my CTA's stores visible
        unsigned g = gen;
        unsigned a = atomicAdd(&bar_cnt, 1u);
        if (a == NCTA - 1) {
            atomicExch(&bar_cnt, 0u);
            __threadfence();
            atomicAdd(&bar_gen, 1u);          // release
        } else {
            while (atomicAdd(&bar_gen, 0u) == g) { /* spin at L2 */ }
        }
        gen = g + 1u;
        __threadfence();                      // acquire
    }
    __syncthreads();
}

// Partial matvec: warp q in 0..3 covers 32 k-values of
//   out[i] = sum_k sv[k] * W[k*128 + i]
// Each lane produces 4 output columns (one float4). Partials -> pb[q*128 + i].
__device__ __forceinline__ void matvec_part(const float4* __restrict__ W4,
                                            const float* __restrict__ sv,
                                            float* __restrict__ pb,
                                            int q, int lane) {
    float4 acc = make_float4(0.f, 0.f, 0.f, 0.f);
    const int kbase = q * 32;
#pragma unroll
    for (int kk = 0; kk < 32; kk++) {
        int k = kbase + kk;
        float v = sv[k];
        float4 wv = W4[k * 32 + lane];
        acc.x = fmaf(v, wv.x, acc.x);
        acc.y = fmaf(v, wv.y, acc.y);
        acc.z = fmaf(v, wv.z, acc.z);
        acc.w = fmaf(v, wv.w, acc.w);
    }
    reinterpret_cast<float4*>(pb + q * 128)[lane] = acc;
}

__device__ __forceinline__ float red4(const float* __restrict__ pb, int i) {
    return pb[i] + pb[128 + i] + pb[256 + i] + pb[384 + i];
}

// 128-dot of a global z row (L1-bypassed) against W_omega, warp-collective.
__device__ __forceinline__ float warp_dot_ldcg(const float* __restrict__ row,
                                               const float* __restrict__ Wo,
                                               int lane) {
    float a = 0.f;
#pragma unroll
    for (int c = 0; c < 4; c++) {
        int i = lane + 32 * c;
        a = fmaf(__ldcg(&row[i]), __ldg(&Wo[i]), a);
    }
#pragma unroll
    for (int o = 16; o > 0; o >>= 1) a += __shfl_down_sync(0xffffffffu, a, o);
    return a;
}

// ---------------- prep: aligned weight copies (scalar loads only) ---------
__global__ void prep_kernel(const float* __restrict__ Wh,
                            const float* __restrict__ We2n,
                            const float* __restrict__ Wrece,
                            const float* __restrict__ Wrecn) {
    int i = blockIdx.x * blockDim.x + threadIdx.x;
    if (i < Hd * Hd) {
        ((float*)g_Wh4)[i]    = __ldg(&Wh[i]);
        ((float*)g_We2n4)[i]  = __ldg(&We2n[i]);
        ((float*)g_Wrece4)[i] = __ldg(&Wrece[i]);
        ((float*)g_Wrecn4)[i] = __ldg(&Wrecn[i]);
    }
}

// ---------------- z0 -> z_buf copy (each launch, deterministic replays) ----
__global__ void copy_z_kernel(const float* __restrict__ z0) {
    size_t n = (size_t)Nn * Hd;
    for (size_t i = (size_t)blockIdx.x * blockDim.x + threadIdx.x; i < n;
         i += (size_t)gridDim.x * blockDim.x)
        z_buf[i] = __ldg(&z0[i]);
}

// ---------------- main persistent kernel ----------------
__global__ void __launch_bounds__(256) dyrep_main(
    const float* __restrict__ tb,      // time_bar [B, N]
    const float* __restrict__ tcur,    // time_cur [B]
    const float* __restrict__ tdelta,  // time_delta [B, 2]
    const int* __restrict__ uu,        // u [B]
    const int* __restrict__ nbi,       // neighbors [B, D]
    const int* __restrict__ ngi,       // neg_nodes [B, NEG]
    const float* __restrict__ Womega, const float* __restrict__ bomega,
    const float* __restrict__ bh,
    const float* __restrict__ be2n,
    const float* __restrict__ brece,
    const float* __restrict__ brecn,
    const float* __restrict__ Wtime,  const float* __restrict__ btime,
    const float* __restrict__ wt_,    const float* __restrict__ alpha_,
    const float* __restrict__ psi_,
    float* __restrict__ out)           // [B + B*NEG]
{
    __shared__ int   sidx[Dd];
    __shared__ int   su;
    __shared__ int   sneg[NEGS];
    __shared__ float sTd[1 + Dd];
    __shared__ __align__(16) float sv[2][Hd];
    __shared__ __align__(16) float pb[2][4 * Hd];
    __shared__ int   sen[2];

    const int cta  = blockIdx.x;
    const int tid  = threadIdx.x;
    const int w    = tid >> 5;
    const int lane = tid & 31;

    const float w_t   = __ldg(wt_);
    const float alpha = __ldg(alpha_);
    const float psi   = __ldg(psi_);
    const float b_om  = __ldg(bomega);

    unsigned gen = 0;
    if (tid == 0) gen = atomicAdd(&bar_gen, 0u);  // sample before first arrival

    for (int t = 0; t < Bb; t++) {
        // ---- prologue: indices and positional td --------------------------
        if (tid < Dd)                 sidx[tid] = __ldg(&nbi[t * Dd + tid]);
        if (tid == Dd)                su        = __ldg(&uu[t]);
        if (tid >= 33 && tid < 33 + NEGS) sneg[tid - 33] = __ldg(&ngi[t * NEGS + (tid - 33)]);
        const float tc = __ldg(&tcur[t]);
        if (tid < 1 + Dd)             sTd[tid] = tc - __ldg(&tb[(size_t)t * Nn + tid]);
        __syncthreads();

        // ---- phase A: pre-update reads + matvec partials ------------------
        if (cta < 16) {
            const int j0 = cta * 2, j1 = j0 + 1;
            const int n0 = sidx[j0], n1 = sidx[j1];
            if (tid < 128) sv[0][tid]       = __ldcg(&z_buf[(size_t)n0 * Hd + tid]);
            else           sv[1][tid - 128] = __ldcg(&z_buf[(size_t)n1 * Hd + (tid - 128)]);
            if (tid == 0) { // last duplicate j wins
                int en = 1;
                for (int j = j0 + 1; j < Dd; j++) if (sidx[j] == n0) en = 0;
                sen[0] = en;
            }
            if (tid == 1) {
                int en = 1;
                for (int j = j1 + 1; j < Dd; j++) if (sidx[j] == n1) en = 0;
                sen[1] = en;
            }
            __syncthreads();
            matvec_part(g_Wrecn4, sv[w >> 2], pb[w >> 2], w & 3, lane);
        } else if (cta == 16) {
            // mean(z_nb) then @ W_h
            if (tid < 128) {
                float acc = 0.f;
#pragma unroll
                for (int r = 0; r < Dd; r++)
                    acc += __ldcg(&z_buf[(size_t)sidx[r] * Hd + tid]);
                sv[0][tid] = acc * (1.0f / 32.0f);
            }
            if (tid == 0) { // any neighbor write to u overrides h_u
                int en = 1;
                for (int j = 0; j < Dd; j++) if (sidx[j] == su) en = 0;
                sen[0] = en;
            }
            __syncthreads();
            if (w < 4) matvec_part(g_Wh4, sv[0], pb[0], w, lane);
        } else if (cta == 17) {
            // s = z_u @ W_e2n + b_e2n   (+ all Hawkes outputs, pre-update)
            if (tid < 128) sv[0][tid] = __ldcg(&z_buf[(size_t)su * Hd + tid]);
            __syncthreads();
            if (w < 4) {
                matvec_part(g_We2n4, sv[0], pb[0], w, lane);
            } else {
                // tasks: 0 = emb_u, 1..5 = negatives
                for (int task = w - 4; task < 6; task += 4) {
                    if (task == 0) {
                        float dot = warp_dot_ldcg(&z_buf[(size_t)su * Hd], Womega, lane);
                        if (lane == 0) {
                            float tsd = tc - __ldg(&tdelta[2 * t]);
                            float g = dot + b_om + alpha * expf(-w_t * tsd);
                            out[t] = psi * softplusf_(g / psi);
                        }
                    } else {
                        int q = task - 1;
                        int node = sneg[q];
                        float dot = warp_dot_ldcg(&z_buf[(size_t)node * Hd], Womega, lane);
                        if (lane == 0) {
                            float tdn = tc - __ldg(&tb[(size_t)t * Nn + node]);
                            float g = dot + b_om + alpha * expf(-w_t * tdn);
                            out[Bb + t * NEGS + q] = psi * softplusf_(g / psi) * (1.0f / NEGS);
                        }
                    }
                }
            }
            __syncthreads();
            if (tid < 128) s_buf[tid] = red4(pb[0], tid) + __ldg(&be2n[tid]);
        } else { // cta == 18: r = z_u @ W_rec_e + b_rec_e
            if (tid < 128) sv[0][tid] = __ldcg(&z_buf[(size_t)su * Hd + tid]);
            __syncthreads();
            if (w < 4) matvec_part(g_Wrece4, sv[0], pb[0], w, lane);
            __syncthreads();
            if (tid < 128) r_buf[tid] = red4(pb[0], tid) + __ldg(&brece[tid]);
        }

        grid_barrier(gen);  // B1: all pre-update reads done; s_buf/r_buf visible

        // ---- phase B: combine, sigmoid, masked writes ---------------------
        if (cta < 16) {
            const int m = tid >> 7;
            const int i = tid & 127;
            const int j = cta * 2 + m;
            const int node = sidx[j];
            float h = __ldcg(&s_buf[i]) + red4(pb[m], i) + __ldg(&brecn[i])
                    + sTd[1 + j] * __ldg(&Wtime[i]) + __ldg(&btime[i]);
            h = sigmoidf_(h);
            if (sen[m]) z_buf[(size_t)node * Hd + i] = h;
        } else if (cta == 16) {
            if (tid < 128) {
                float h = red4(pb[0], tid) + __ldg(&bh[tid]) + __ldcg(&r_buf[tid])
                        + sTd[0] * __ldg(&Wtime[tid]) + __ldg(&btime[tid]);
                h = sigmoidf_(h);
                if (sen[0]) z_buf[(size_t)su * Hd + tid] = h;
            }
        }
        // CTAs 17/18 idle in phase B

        grid_barrier(gen);  // B2: writes visible before next step's reads
    }
}

// ---------------- launch ----------------
extern "C" void kernel_launch(void* const* d_in, const int* in_sizes, int n_in,
                              void* d_out, int out_size) {
    (void)in_sizes; (void)n_in; (void)out_size;
    const float* time_bar   = (const float*)d_in[0];
    const float* time_cur   = (const float*)d_in[1];
    const float* time_delta = (const float*)d_in[2];
    const int*   u          = (const int*)d_in[3];
    const int*   neighbors  = (const int*)d_in[4];
    const int*   neg_nodes  = (const int*)d_in[5];
    const float* z0         = (const float*)d_in[6];
    const float* W_omega    = (const float*)d_in[7];
    const float* b_omega    = (const float*)d_in[8];
    const float* W_h        = (const float*)d_in[9];
    const float* b_h        = (const float*)d_in[10];
    const float* W_e2n      = (const float*)d_in[11];
    const float* b_e2n      = (const float*)d_in[12];
    const float* W_rec_e    = (const float*)d_in[13];
    const float* b_rec_e    = (const float*)d_in[14];
    const float* W_rec_n    = (const float*)d_in[15];
    const float* b_rec_n    = (const float*)d_in[16];
    const float* W_time     = (const float*)d_in[17];
    const float* b_time     = (const float*)d_in[18];
    const float* w_t        = (const float*)d_in[19];
    const float* alpha      = (const float*)d_in[20];
    const float* psi        = (const float*)d_in[21];

    prep_kernel<<<64, 256>>>(W_h, W_e2n, W_rec_e, W_rec_n);
    copy_z_kernel<<<2048, 256>>>(z0);
    dyrep_main<<<NCTA, 256>>>(time_bar, time_cur, time_delta, u, neighbors,
                              neg_nodes, W_omega, b_omega, b_h,
                              b_e2n, b_rec_e, b_rec_n,
                              W_time, b_time, w_t, alpha, psi, (float*)d_out);
}

// round 6
// speedup vs baseline: 6.7098x; 6.7098x over previous
#include <cuda_runtime.h>
#include <math.h>

#define Nn   100000
#define Hd   128
#define Bb   512
#define Dd   32
#define NEGS 5
#define Tt   38     // touches: u + 32 nb + 5 neg
#define Ww   33     // writes:  u + 32 nb
#define NCTA 128
#define TPB  1024

// ---------------- device scratch ----------------
__device__ float4 z_buf4[(size_t)Nn * (Hd / 4)];
#define z_buf ((float*)z_buf4)
__device__ float4 g_Wh4[Hd * (Hd / 4)];
__device__ float4 g_We2n4[Hd * (Hd / 4)];
__device__ float4 g_Wrece4[Hd * (Hd / 4)];
__device__ float4 g_Wrecn4[Hd * (Hd / 4)];
__device__ unsigned g_conf[Bb * 16];   // bitmatrix: row t2, bit t1 (t1<t2)
__device__ int g_order[Bb];
__device__ int g_lvl_start[Bb + 1];
__device__ int g_nlv;
__device__ unsigned bar_cnt, bar_gen;

__device__ __forceinline__ float sigmoidf_(float x) { return 1.0f / (1.0f + expf(-x)); }
__device__ __forceinline__ float softplusf_(float x) {
    return fmaxf(x, 0.0f) + log1pf(expf(-fabsf(x)));
}

__device__ __forceinline__ void grid_barrier(unsigned& gen) {
    __syncthreads();
    if (threadIdx.x == 0) {
        __threadfence();
        unsigned g = gen;
        if (atomicAdd(&bar_cnt, 1u) == NCTA - 1) {
            atomicExch(&bar_cnt, 0u);
            __threadfence();
            atomicAdd(&bar_gen, 1u);
        } else {
            while (atomicAdd(&bar_gen, 0u) == g) {}
        }
        gen = g + 1u;
        __threadfence();
    }
    __syncthreads();
}

// ---- 1: aligned weight copies (scalar loads; d_in only 4B-aligned) ----
__global__ void prep_kernel(const float* __restrict__ Wh, const float* __restrict__ We2n,
                            const float* __restrict__ Wrece, const float* __restrict__ Wrecn) {
    int i = blockIdx.x * blockDim.x + threadIdx.x;
    if (i < Hd * Hd) {
        ((float*)g_Wh4)[i]    = __ldg(&Wh[i]);
        ((float*)g_We2n4)[i]  = __ldg(&We2n[i]);
        ((float*)g_Wrece4)[i] = __ldg(&Wrece[i]);
        ((float*)g_Wrecn4)[i] = __ldg(&Wrecn[i]);
    }
}

// ---- 2: restore touched z rows from z0 (one warp per (step,touch)) ----
__global__ void restore_kernel(const float* __restrict__ z0, const int* __restrict__ uu,
                               const int* __restrict__ nbi, const int* __restrict__ ngi) {
    int gw = (blockIdx.x * blockDim.x + threadIdx.x) >> 5;
    int lane = threadIdx.x & 31;
    int nw = (gridDim.x * blockDim.x) >> 5;
    for (int e = gw; e < Bb * Tt; e += nw) {
        int t = e / Tt, i = e - t * Tt;
        int node = (i == 0) ? __ldg(&uu[t])
                 : (i < Ww) ? __ldg(&nbi[t * Dd + i - 1])
                            : __ldg(&ngi[t * NEGS + i - Ww]);
        const float* s = z0 + (size_t)node * Hd + lane * 4;
        float4 v;
        v.x = __ldg(s); v.y = __ldg(s + 1); v.z = __ldg(s + 2); v.w = __ldg(s + 3);
        z_buf4[(size_t)node * 32 + lane] = v;
    }
}

// ---- 3: conflict bitmatrix (CTA t2, hash of its touch set) ----
__global__ void conflict_kernel(const int* __restrict__ uu, const int* __restrict__ nbi,
                                const int* __restrict__ ngi) {
    __shared__ int tab_id[64], tab_fl[64];
    int t2 = blockIdx.x, tid = threadIdx.x;
    int lane = tid & 31, wid = tid >> 5;
    if (tid < 64) { tab_id[tid] = -1; tab_fl[tid] = 0; }
    __syncthreads();
    if (tid == 0) {
        for (int i = 0; i < Tt; i++) {
            int a = (i == 0) ? __ldg(&uu[t2])
                  : (i < Ww) ? __ldg(&nbi[t2 * Dd + i - 1])
                             : __ldg(&ngi[t2 * NEGS + i - Ww]);
            int fl = (i < Ww), h = a & 63;
            for (;;) {
                int v = tab_id[h];
                if (v < 0)  { tab_id[h] = a; tab_fl[h] = fl; break; }
                if (v == a) { tab_fl[h] |= fl; break; }
                h = (h + 1) & 63;
            }
        }
    }
    __syncthreads();
    for (int rep = 0; rep < 2; rep++) {
        int t1 = tid + rep * 256, bit = 0;
        if (t1 < t2) {
            for (int i = 0; i < Tt && !bit; i++) {
                int a = (i == 0) ? __ldg(&uu[t1])
                      : (i < Ww) ? __ldg(&nbi[t1 * Dd + i - 1])
                                 : __ldg(&ngi[t1 * NEGS + i - Ww]);
                int fl = (i < Ww), h = a & 63;
                for (;;) {
                    int v = tab_id[h];
                    if (v < 0) break;
                    if (v == a) { if (fl | tab_fl[h]) bit = 1; break; }
                    h = (h + 1) & 63;
                }
            }
        }
        unsigned bal = __ballot_sync(0xffffffffu, bit);
        if (lane == 0) g_conf[t2 * 16 + wid + 8 * rep] = bal;
    }
}

// ---- 4: longest-path levels + counting sort ----
__global__ void levels_kernel() {
    __shared__ unsigned lv[Bb];
    __shared__ int chg;
    __shared__ unsigned cnt[Bb + 1];
    __shared__ unsigned maxl;
    int t = threadIdx.x;
    unsigned row[16];
#pragma unroll
    for (int j = 0; j < 16; j++) row[j] = g_conf[t * 16 + j];
    lv[t] = 1;
    if (t == 0) maxl = 0;
    __syncthreads();
    for (;;) {
        if (t == 0) chg = 0;
        __syncthreads();
        unsigned m = 0;
#pragma unroll
        for (int j = 0; j < 16; j++) {
            unsigned w = row[j];
            while (w) { int b = __ffs(w) - 1; w &= w - 1;
                        unsigned l = lv[j * 32 + b]; if (l > m) m = l; }
        }
        if (m + 1 > lv[t]) { lv[t] = m + 1; chg = 1; }
        __syncthreads();
        int done = !chg;
        __syncthreads();
        if (done) break;
    }
    if (t == 0) cnt[Bb] = 0;
    cnt[t] = 0;
    __syncthreads();
    atomicAdd(&cnt[lv[t]], 1u);
    atomicMax(&maxl, lv[t]);
    __syncthreads();
    if (t == 0) {
        unsigned s = 0, M = maxl;
        for (unsigned l = 1; l <= M; l++) {
            unsigned c = cnt[l]; cnt[l] = s; g_lvl_start[l - 1] = (int)s; s += c;
        }
        g_lvl_start[M] = Bb;
        g_nlv = (int)M;
    }
    __syncthreads();
    g_order[atomicAdd(&cnt[lv[t]], 1u)] = t;
}

// ---- 5: main — one CTA per step, levels in waves ----
__global__ void __launch_bounds__(TPB, 1) dyrep_main(
    const float* __restrict__ tb, const float* __restrict__ tcur,
    const float* __restrict__ tdelta, const int* __restrict__ uu,
    const int* __restrict__ nbi, const int* __restrict__ ngi,
    const float* __restrict__ Womega, const float* __restrict__ bomega,
    const float* __restrict__ bh, const float* __restrict__ be2n,
    const float* __restrict__ brece, const float* __restrict__ brecn,
    const float* __restrict__ Wtime, const float* __restrict__ btime,
    const float* __restrict__ wt_, const float* __restrict__ alpha_,
    const float* __restrict__ psi_, float* __restrict__ out)
{
    __shared__ float4 z_sh4[33][32];                 // rows 0..31 nb, 32 = u
    __shared__ float4 pbs4[4][32], pbr4[4][32], pbh4[4][32];
    __shared__ float4 s_sh4[32];
    __shared__ float  mean_sh[Hd];
    __shared__ float  Wo_s[Hd], Wt_s[Hd], bt_s[Hd], brn_s[Hd], be2n_s[Hd], brece_s[Hd], bh_s[Hd];
    __shared__ int    nb_sh[Dd], neg_sh[NEGS], su_s;
    __shared__ unsigned en_mask_s;
    __shared__ int    en_u_s;
    __shared__ float  td_sh[33];

    const int tid = threadIdx.x, wid = tid >> 5, lane = tid & 31, bid = blockIdx.x;
    const float* zsh = (const float*)z_sh4;
    const float* s_sh = (const float*)s_sh4;

    const float w_t = __ldg(wt_), alpha = __ldg(alpha_), psi = __ldg(psi_), b_om = __ldg(bomega);

    if (tid < Hd) {
        Wo_s[tid] = __ldg(&Womega[tid]);  Wt_s[tid] = __ldg(&Wtime[tid]);
        bt_s[tid] = __ldg(&btime[tid]);   brn_s[tid] = __ldg(&brecn[tid]);
        be2n_s[tid] = __ldg(&be2n[tid]);  brece_s[tid] = __ldg(&brece[tid]);
        bh_s[tid] = __ldg(&bh[tid]);
    }
    unsigned gen = 0;
    if (tid == 0) gen = atomicAdd(&bar_gen, 0u);
    __syncthreads();

    const int nlv = g_nlv;
    for (int lvi = 0; lvi < nlv; lvi++) {
        const int s0 = g_lvl_start[lvi], s1 = g_lvl_start[lvi + 1];
        for (int it = s0 + bid; it < s1; it += NCTA) {
            const int t = g_order[it];
            const float tc = __ldg(&tcur[t]);

            // P0: indices + positional td
            if (tid < Dd)                         nb_sh[tid] = __ldg(&nbi[t * Dd + tid]);
            else if (tid == Dd)                   su_s = __ldg(&uu[t]);
            else if (tid < Dd + 1 + NEGS)         neg_sh[tid - 33] = __ldg(&ngi[t * NEGS + tid - 33]);
            if (tid >= 64 && tid < 97)            td_sh[tid - 64] = tc - __ldg(&tb[(size_t)t * Nn + tid - 64]);
            __syncthreads();

            // z rows -> smem (pre-update), masks
            z_sh4[wid][lane] = __ldcg(&z_buf4[(size_t)nb_sh[wid] * 32 + lane]);
            if (tid < 32) z_sh4[32][tid] = __ldcg(&z_buf4[(size_t)su_s * 32 + tid]);
            if (wid == 0) {
                int nbj = nb_sh[lane], dup = 0;
                for (int j2 = lane + 1; j2 < Dd; j2++) dup |= (nb_sh[j2] == nbj);
                unsigned bal  = __ballot_sync(0xffffffffu, !dup);
                unsigned balu = __ballot_sync(0xffffffffu, nbj == su_s);
                if (lane == 0) { en_mask_s = bal; en_u_s = (balu == 0); }
            }
            __syncthreads();

            if (tid < Hd) {
                float a = 0.f;
#pragma unroll
                for (int r = 0; r < Dd; r++) a += zsh[r * Hd + tid];
                mean_sh[tid] = a * (1.0f / 32.0f);
            }
            __syncthreads();

            // Phase A: GEMM (warps 0..7) + matvec partials + hawkes
            float4 a0, a1, a2, a3;
            if (wid < 8) {
                a0 = a1 = a2 = a3 = make_float4(0.f, 0.f, 0.f, 0.f);
                const int j0 = wid * 4;
#pragma unroll 4
                for (int k = 0; k < Hd; k++) {
                    float4 wv = __ldg(&g_Wrecn4[k * 32 + lane]);
                    float z0v = zsh[(j0 + 0) * Hd + k], z1v = zsh[(j0 + 1) * Hd + k];
                    float z2v = zsh[(j0 + 2) * Hd + k], z3v = zsh[(j0 + 3) * Hd + k];
                    a0.x = fmaf(z0v, wv.x, a0.x); a0.y = fmaf(z0v, wv.y, a0.y);
                    a0.z = fmaf(z0v, wv.z, a0.z); a0.w = fmaf(z0v, wv.w, a0.w);
                    a1.x = fmaf(z1v, wv.x, a1.x); a1.y = fmaf(z1v, wv.y, a1.y);
                    a1.z = fmaf(z1v, wv.z, a1.z); a1.w = fmaf(z1v, wv.w, a1.w);
                    a2.x = fmaf(z2v, wv.x, a2.x); a2.y = fmaf(z2v, wv.y, a2.y);
                    a2.z = fmaf(z2v, wv.z, a2.z); a2.w = fmaf(z2v, wv.w, a2.w);
                    a3.x = fmaf(z3v, wv.x, a3.x); a3.y = fmaf(z3v, wv.y, a3.y);
                    a3.z = fmaf(z3v, wv.z, a3.z); a3.w = fmaf(z3v, wv.w, a3.w);
                }
            } else if (wid < 20) {
                const int q = (wid - 8) & 3;
                const float4* W4 = (wid < 12) ? g_We2n4 : (wid < 16) ? g_Wrece4 : g_Wh4;
                const float* v = (wid < 16) ? (zsh + 32 * Hd) : mean_sh;
                float4 acc = make_float4(0.f, 0.f, 0.f, 0.f);
#pragma unroll
                for (int kk = 0; kk < 32; kk++) {
                    int k = q * 32 + kk;
                    float vv = v[k];
                    float4 wv = __ldg(&W4[k * 32 + lane]);
                    acc.x = fmaf(vv, wv.x, acc.x); acc.y = fmaf(vv, wv.y, acc.y);
                    acc.z = fmaf(vv, wv.z, acc.z); acc.w = fmaf(vv, wv.w, acc.w);
                }
                if (wid < 12) pbs4[q][lane] = acc;
                else if (wid < 16) pbr4[q][lane] = acc;
                else pbh4[q][lane] = acc;
            } else if (wid == 20) {
                float a = 0.f;
#pragma unroll
                for (int c = 0; c < 4; c++) {
                    int i = lane + 32 * c;
                    a = fmaf(zsh[32 * Hd + i], Wo_s[i], a);
                }
#pragma unroll
                for (int o = 16; o > 0; o >>= 1) a += __shfl_down_sync(0xffffffffu, a, o);
                if (lane == 0) {
                    float g = a + b_om + alpha * expf(-w_t * (tc - __ldg(&tdelta[2 * t])));
                    out[t] = psi * softplusf_(g / psi);
                }
            } else if (wid < 21 + NEGS) {
                const int q = wid - 21, node = neg_sh[q];
                float a = 0.f;
#pragma unroll
                for (int c = 0; c < 4; c++) {
                    int i = lane + 32 * c;
                    a = fmaf(__ldcg(&z_buf[(size_t)node * Hd + i]), Wo_s[i], a);
                }
#pragma unroll
                for (int o = 16; o > 0; o >>= 1) a += __shfl_down_sync(0xffffffffu, a, o);
                if (lane == 0) {
                    float tdn = tc - __ldg(&tb[(size_t)t * Nn + node]);
                    float g = a + b_om + alpha * expf(-w_t * tdn);
                    out[Bb + t * NEGS + q] = psi * softplusf_(g / psi) * (1.0f / NEGS);
                }
            }
            __syncthreads();

            // Phase B: s vector; h_u combine + write
            if (tid < Hd) {
                const float* ps = (const float*)pbs4;
                ((float*)s_sh4)[tid] = ps[tid] + ps[Hd + tid] + ps[2 * Hd + tid] + ps[3 * Hd + tid]
                                       + be2n_s[tid];
            } else if (tid < 2 * Hd) {
                const int i = tid - Hd;
                const float* pr = (const float*)pbr4;
                const float* ph = (const float*)pbh4;
                float h = ph[i] + ph[Hd + i] + ph[2 * Hd + i] + ph[3 * Hd + i] + bh_s[i]
                        + pr[i] + pr[Hd + i] + pr[2 * Hd + i] + pr[3 * Hd + i] + brece_s[i]
                        + td_sh[0] * Wt_s[i] + bt_s[i];
                if (en_u_s) z_buf[(size_t)su_s * Hd + i] = sigmoidf_(h);
            }
            __syncthreads();

            // Phase C: neighbor rows combine + masked writes
            if (wid < 8) {
                const int j0 = wid * 4, c0 = lane * 4;
                float sx = s_sh[c0] + brn_s[c0] + bt_s[c0];
                float sy = s_sh[c0 + 1] + brn_s[c0 + 1] + bt_s[c0 + 1];
                float sz = s_sh[c0 + 2] + brn_s[c0 + 2] + bt_s[c0 + 2];
                float sw = s_sh[c0 + 3] + brn_s[c0 + 3] + bt_s[c0 + 3];
                float wx = Wt_s[c0], wy = Wt_s[c0 + 1], wz = Wt_s[c0 + 2], ww = Wt_s[c0 + 3];
                float4 aa[4] = {a0, a1, a2, a3};
#pragma unroll
                for (int r = 0; r < 4; r++) {
                    const int j = j0 + r;
                    if ((en_mask_s >> j) & 1u) {
                        float td = td_sh[1 + j];
                        float4 h;
                        h.x = sigmoidf_(aa[r].x + sx + td * wx);
                        h.y = sigmoidf_(aa[r].y + sy + td * wy);
                        h.z = sigmoidf_(aa[r].z + sz + td * wz);
                        h.w = sigmoidf_(aa[r].w + sw + td * ww);
                        z_buf4[(size_t)nb_sh[j] * 32 + lane] = h;
                    }
                }
            }
            __syncthreads();
        }
        grid_barrier(gen);
    }
}

// ---------------- launch ----------------
extern "C" void kernel_launch(void* const* d_in, const int* in_sizes, int n_in,
                              void* d_out, int out_size) {
    (void)in_sizes; (void)n_in; (void)out_size;
    const float* time_bar   = (const float*)d_in[0];
    const float* time_cur   = (const float*)d_in[1];
    const float* time_delta = (const float*)d_in[2];
    const int*   u          = (const int*)d_in[3];
    const int*   neighbors  = (const int*)d_in[4];
    const int*   neg_nodes  = (const int*)d_in[5];
    const float* z0         = (const float*)d_in[6];
    const float* W_omega    = (const float*)d_in[7];
    const float* b_omega    = (const float*)d_in[8];
    const float* W_h        = (const float*)d_in[9];
    const float* b_h        = (const float*)d_in[10];
    const float* W_e2n      = (const float*)d_in[11];
    const float* b_e2n      = (const float*)d_in[12];
    const float* W_rec_e    = (const float*)d_in[13];
    const float* b_rec_e    = (const float*)d_in[14];
    const float* W_rec_n    = (const float*)d_in[15];
    const float* b_rec_n    = (const float*)d_in[16];
    const float* W_time     = (const float*)d_in[17];
    const float* b_time     = (const float*)d_in[18];
    const float* w_t        = (const float*)d_in[19];
    const float* alpha      = (const float*)d_in[20];
    const float* psi        = (const float*)d_in[21];

    prep_kernel<<<64, 256>>>(W_h, W_e2n, W_rec_e, W_rec_n);
    restore_kernel<<<512, 256>>>(z0, u, neighbors, neg_nodes);
    conflict_kernel<<<Bb, 256>>>(u, neighbors, neg_nodes);
    levels_kernel<<<1, Bb>>>();
    dyrep_main<<<NCTA, TPB>>>(time_bar, time_cur, time_delta, u, neighbors,
                              neg_nodes, W_omega, b_omega, b_h, b_e2n, b_rec_e,
                              b_rec_n, W_time, b_time, w_t, alpha, psi,
                              (float*)d_out);
}

// round 8
// speedup vs baseline: 8.2256x; 1.2259x over previous
#include <cuda_runtime.h>
#include <math.h>

#define Nn    100000
#define Hd    128
#define Bb    512
#define Dd    32
#define NEGS  5
#define Tt    38     // touches: u + 32 nb + 5 neg
#define Ww    33     // writes:  u + 32 nb
#define NCTA  128
#define TPB   256
#define WSTEP 25     // steps per wave (step-aligned waves)
#define WPAIR 125    // pairs per wave = WSTEP*5

// ---------------- device scratch ----------------
__device__ float4 z_buf4[(size_t)Nn * 32];
#define z_buf ((float*)z_buf4)
__device__ float4 g_Wh4[4096], g_We2n4[4096], g_Wrece4[4096], g_Wrecn4[4096];
__device__ unsigned g_conf[Bb * 16];   // bitmatrix: row t2, bit t1 (t1<t2)
__device__ int g_order[Bb];
__device__ int g_lvl_start[Bb + 1];
__device__ int g_nlv;
__device__ unsigned bar_leaf[16], bar_root, bar_gen;

__device__ __forceinline__ float sigmoidf_(float x) { return 1.0f / (1.0f + expf(-x)); }
__device__ __forceinline__ float softplusf_(float x) {
    return fmaxf(x, 0.0f) + log1pf(expf(-fabsf(x)));
}
__device__ __forceinline__ void ffma2(unsigned long long& d, unsigned long long a,
                                      unsigned long long b, unsigned long long c) {
    asm("fma.rn.f32x2 %0, %1, %2, %3;" : "=l"(d) : "l"(a), "l"(b), "l"(c));
}
__device__ __forceinline__ unsigned long long packf2(float v) {
    unsigned long long r;
    asm("mov.b64 %0, {%1, %1};" : "=l"(r) : "f"(v));
    return r;
}
__device__ __forceinline__ void unpackf2(unsigned long long p, float& lo, float& hi) {
    asm("mov.b64 {%0, %1}, %2;" : "=f"(lo), "=f"(hi) : "l"(p));
}

// tree grid barrier: 16 leaves x 8 CTAs; spinners do volatile L2 reads (no atomics)
__device__ __forceinline__ void grid_barrier(unsigned& gen, int bid) {
    __syncthreads();
    if (threadIdx.x == 0) {
        __threadfence();
        unsigned g = gen;
        if (atomicAdd(&bar_leaf[bid & 15], 1u) == 7u) {
            atomicExch(&bar_leaf[bid & 15], 0u);
            if (atomicAdd(&bar_root, 1u) == 15u) {
                atomicExch(&bar_root, 0u);
                __threadfence();
                atomicAdd(&bar_gen, 1u);
            }
        }
        while (*(volatile unsigned*)&bar_gen == g) {}
        gen = g + 1u;
        __threadfence();
    }
    __syncthreads();
}

// warp q of 4 covers k in [32q,32q+32) of out[i] = sum_k sv[k]*W[k*128+i]
__device__ __forceinline__ void matvec_part(const float4* __restrict__ W4,
                                            const float* __restrict__ sv,
                                            float* __restrict__ pb, int q, int lane) {
    float4 acc = make_float4(0.f, 0.f, 0.f, 0.f);
#pragma unroll
    for (int kk = 0; kk < 32; kk++) {
        int k = q * 32 + kk;
        float v = sv[k];
        float4 wv = W4[k * 32 + lane];
        acc.x = fmaf(v, wv.x, acc.x); acc.y = fmaf(v, wv.y, acc.y);
        acc.z = fmaf(v, wv.z, acc.z); acc.w = fmaf(v, wv.w, acc.w);
    }
    reinterpret_cast<float4*>(pb + q * 128)[lane] = acc;
}

// ---- 1: fused setup: conflict bitmatrix + weight copies + z-row restore ----
__global__ void setup_kernel(const float* __restrict__ z0,
                             const int* __restrict__ uu, const int* __restrict__ nbi,
                             const int* __restrict__ ngi,
                             const float* __restrict__ Wh, const float* __restrict__ We2n,
                             const float* __restrict__ Wrece, const float* __restrict__ Wrecn) {
    __shared__ int tab_id[64], tab_fl[64];
    const int t2 = blockIdx.x, tid = threadIdx.x;
    const int lane = tid & 31, wid = tid >> 5;

    if (tid < 64) { tab_id[tid] = -1; tab_fl[tid] = 0; }
    __syncthreads();
    if (tid == 0) {
        for (int i = 0; i < Tt; i++) {
            int a = (i == 0) ? __ldg(&uu[t2])
                  : (i < Ww) ? __ldg(&nbi[t2 * Dd + i - 1])
                             : __ldg(&ngi[t2 * NEGS + i - Ww]);
            int fl = (i < Ww), h = a & 63;
            for (;;) {
                int v = tab_id[h];
                if (v < 0)  { tab_id[h] = a; tab_fl[h] = fl; break; }
                if (v == a) { tab_fl[h] |= fl; break; }
                h = (h + 1) & 63;
            }
        }
    }
    __syncthreads();
    for (int rep = 0; rep < 2; rep++) {
        int t1 = tid + rep * 256, bit = 0;
        if (t1 < t2) {
            for (int i = 0; i < Tt && !bit; i++) {
                int a = (i == 0) ? __ldg(&uu[t1])
                      : (i < Ww) ? __ldg(&nbi[t1 * Dd + i - 1])
                                 : __ldg(&ngi[t1 * NEGS + i - Ww]);
                int fl = (i < Ww), h = a & 63;
                for (;;) {
                    int v = tab_id[h];
                    if (v < 0) break;
                    if (v == a) { if (fl | tab_fl[h]) bit = 1; break; }
                    h = (h + 1) & 63;
                }
            }
        }
        unsigned bal = __ballot_sync(0xffffffffu, bit);
        if (lane == 0) g_conf[t2 * 16 + wid + 8 * rep] = bal;
    }

    int gidx = t2 * TPB + tid;
    if (gidx < Hd * Hd) {
        ((float*)g_Wh4)[gidx]    = __ldg(&Wh[gidx]);
        ((float*)g_We2n4)[gidx]  = __ldg(&We2n[gidx]);
        ((float*)g_Wrece4)[gidx] = __ldg(&Wrece[gidx]);
        ((float*)g_Wrecn4)[gidx] = __ldg(&Wrecn[gidx]);
    }

    int gw = (t2 * TPB + tid) >> 5;
    int nw = (gridDim.x * TPB) >> 5;
    for (int e = gw; e < Bb * Tt; e += nw) {
        int t = e / Tt, i = e - t * Tt;
        int node = (i == 0) ? __ldg(&uu[t])
                 : (i < Ww) ? __ldg(&nbi[t * Dd + i - 1])
                            : __ldg(&ngi[t * NEGS + i - Ww]);
        const float* s = z0 + (size_t)node * Hd + lane * 4;
        float4 v;
        v.x = __ldg(s); v.y = __ldg(s + 1); v.z = __ldg(s + 2); v.w = __ldg(s + 3);
        z_buf4[(size_t)node * 32 + lane] = v;
    }
}

// ---- 2: exact longest-path levels, warp-serial chunks (NO spins) + sort ----
__global__ void levels_kernel() {
    __shared__ unsigned lv[Bb];
    __shared__ unsigned cnt[Bb + 1];
    __shared__ unsigned maxl;
    const int t = threadIdx.x, lane = t & 31, ch = t >> 5;
    unsigned row[16];
#pragma unroll
    for (int j = 0; j < 16; j++) row[j] = g_conf[t * 16 + j];
    if (t == 0) maxl = 0;
    __syncthreads();
    unsigned mylvl = 0;
    for (int r = 0; r < 16; r++) {
        if (ch == r) {
            unsigned m = 0;
            for (int j = 0; j < r; j++) {          // preds in finished chunks
                unsigned wb = row[j];
                while (wb) {
                    int b = __ffs(wb) - 1; wb &= wb - 1;
                    unsigned l = lv[j * 32 + b];
                    if (l > m) m = l;
                }
            }
            unsigned inw = row[r];                 // in-chunk preds (bits < lane)
            for (int p = 0; p < 32; p++) {         // serial resolve within warp
                if (lane == p) mylvl = m + 1u;
                unsigned v = __shfl_sync(0xffffffffu, mylvl, p);
                if (lane > p && ((inw >> p) & 1u) && v > m) m = v;
            }
            lv[t] = mylvl;
        }
        __syncthreads();
    }
    cnt[t] = 0;
    if (t == 0) cnt[Bb] = 0;
    __syncthreads();
    atomicAdd(&cnt[mylvl], 1u);
    atomicMax(&maxl, mylvl);
    __syncthreads();
    if (t == 0) {
        unsigned s = 0, M = maxl;
        for (unsigned l = 1; l <= M; l++) {
            unsigned c = cnt[l]; cnt[l] = s; g_lvl_start[l - 1] = (int)s; s += c;
        }
        g_lvl_start[M] = Bb;
        g_nlv = (int)M;
    }
    __syncthreads();
    g_order[atomicAdd(&cnt[mylvl], 1u)] = t;
}

// ---- 3: main — 5 CTAs/step, two-phase staged writes, step-aligned waves ----
__global__ void __launch_bounds__(TPB, 1) dyrep_main(
    const float* __restrict__ tb, const float* __restrict__ tcur,
    const float* __restrict__ tdelta, const int* __restrict__ uu,
    const int* __restrict__ nbi, const int* __restrict__ ngi,
    const float* __restrict__ Womega, const float* __restrict__ bomega,
    const float* __restrict__ bh, const float* __restrict__ be2n,
    const float* __restrict__ brece, const float* __restrict__ brecn,
    const float* __restrict__ Wtime, const float* __restrict__ btime,
    const float* __restrict__ wt_, const float* __restrict__ alpha_,
    const float* __restrict__ psi_, float* __restrict__ out)
{
    __shared__ int    nb_sh[Dd], su_s, neg_sh[NEGS];
    __shared__ float4 znb4[8][32];        // gemm: 8 nb rows | hub: 5 neg rows
    __shared__ float4 zu4[32];
    __shared__ float4 pbA4[4][32], pbB4[4][32];
    __shared__ float  s_sh[Hd];
    __shared__ float  m_part[2 * Hd];
    __shared__ float  mean_sh[Hd];
    __shared__ float  td_s[8];
    __shared__ unsigned en_s;
    __shared__ int    stg_n, stg_node[8];
    __shared__ float4 stg_h4[8][32];
    __shared__ float  Wo_s[Hd], Wt_s[Hd], bt_s[Hd], brn_s[Hd], be2n_s[Hd], brece_s[Hd], bh_s[Hd];

    const int tid = threadIdx.x, wid = tid >> 5, lane = tid & 31, bid = blockIdx.x;
    const float w_t = __ldg(wt_), alpha = __ldg(alpha_), psi = __ldg(psi_), b_om = __ldg(bomega);

    if (tid < Hd) {
        Wo_s[tid] = __ldg(&Womega[tid]); Wt_s[tid] = __ldg(&Wtime[tid]);
        bt_s[tid] = __ldg(&btime[tid]);  brn_s[tid] = __ldg(&brecn[tid]);
        be2n_s[tid] = __ldg(&be2n[tid]); brece_s[tid] = __ldg(&brece[tid]);
        bh_s[tid] = __ldg(&bh[tid]);
    }
    unsigned gen = 0;
    if (tid == 0) gen = *(volatile unsigned*)&bar_gen;
    __syncthreads();

    int staged = 0;
    const int nlv = g_nlv;
    for (int lvi = 0; lvi < nlv; lvi++) {
        const int s0 = g_lvl_start[lvi];
        const int w  = g_lvl_start[lvi + 1] - s0;
        const int npairs = w * 5;
        const int nwave = (w + WSTEP - 1) / WSTEP;
        for (int k = 0; k < nwave; k++) {
            // ---- phase B of previous wave (disjoint rows from this wave's reads)
            if (staged) {
                if (wid < stg_n && ((en_s >> wid) & 1u))
                    z_buf4[(size_t)stg_node[wid] * 32 + lane] = stg_h4[wid][lane];
                staged = 0;
            }
            __syncthreads();   // protect staging reuse (uniform: staged is CTA-uniform)

            const int pi = k * WPAIR + bid;
            if (bid < WPAIR && pi < npairs) {
                const int t = g_order[s0 + pi / 5];
                const int role = pi - (pi / 5) * 5;
                const float tc = __ldg(&tcur[t]);

                if (role < 4) {
                    // ===== GEMM role: rows [8*role, 8*role+8) =====
                    if (tid < Dd)       nb_sh[tid] = __ldg(&nbi[t * Dd + tid]);
                    else if (tid == Dd) su_s = __ldg(&uu[t]);
                    __syncthreads();
                    const int j0 = role * 8;
                    znb4[wid][lane] = __ldcg(&z_buf4[(size_t)nb_sh[j0 + wid] * 32 + lane]);
                    if (tid < 32) zu4[tid] = __ldcg(&z_buf4[(size_t)su_s * 32 + tid]);
                    else if (tid < 40) {
                        td_s[tid - 32] = tc - __ldg(&tb[(size_t)t * Nn + 1 + j0 + tid - 32]);
                        stg_node[tid - 32] = nb_sh[j0 + tid - 32];
                    }
                    __syncthreads();
                    if (wid == 0) {   // duplicate mask: last j wins
                        int nbj = nb_sh[lane], dup = 0;
                        for (int j2 = lane + 1; j2 < Dd; j2++) dup |= (nb_sh[j2] == nbj);
                        unsigned bal = __ballot_sync(0xffffffffu, !dup);
                        if (lane == 0) { en_s = (bal >> j0) & 0xffu; stg_n = 8; }
                    }
                    if (wid >= 4)  // s = z_u @ W_e2n (warps 4-7; warp0 does mask)
                        matvec_part(g_We2n4, (const float*)zu4, (float*)pbA4, wid - 4, lane);
                    __syncthreads();
                    if (tid < Hd) {
                        const float* pa = (const float*)pbA4;
                        s_sh[tid] = pa[tid] + pa[Hd + tid] + pa[2 * Hd + tid] + pa[3 * Hd + tid]
                                  + be2n_s[tid] + brn_s[tid] + bt_s[tid];
                    }
                    __syncthreads();
                    // row GEMM: warp w -> row j0+w, packed f32x2
                    unsigned long long acc01 = 0ull, acc23 = 0ull;
                    const float* zr = (const float*)znb4[wid];
                    const ulonglong2* W2 = reinterpret_cast<const ulonglong2*>(g_Wrecn4);
#pragma unroll 8
                    for (int k2 = 0; k2 < Hd; k2++) {
                        unsigned long long zz = packf2(zr[k2]);
                        ulonglong2 wv = W2[k2 * 32 + lane];
                        ffma2(acc01, zz, wv.x, acc01);
                        ffma2(acc23, zz, wv.y, acc23);
                    }
                    float ax, ay, az, aw;
                    unpackf2(acc01, ax, ay); unpackf2(acc23, az, aw);
                    const int c0 = lane * 4;
                    const float td = td_s[wid];
                    float4 h;
                    h.x = sigmoidf_(ax + s_sh[c0]     + td * Wt_s[c0]);
                    h.y = sigmoidf_(ay + s_sh[c0 + 1] + td * Wt_s[c0 + 1]);
                    h.z = sigmoidf_(az + s_sh[c0 + 2] + td * Wt_s[c0 + 2]);
                    h.w = sigmoidf_(aw + s_sh[c0 + 3] + td * Wt_s[c0 + 3]);
                    stg_h4[wid][lane] = h;
                    staged = 1;
                } else {
                    // ===== hub role: mean, W_h, W_rec_e, h_u, hawkes =====
                    if (tid < Dd)       nb_sh[tid] = __ldg(&nbi[t * Dd + tid]);
                    else if (tid == Dd) su_s = __ldg(&uu[t]);
                    else if (tid < Dd + 1 + NEGS) neg_sh[tid - 33] = __ldg(&ngi[t * NEGS + tid - 33]);
                    __syncthreads();
                    if (wid < NEGS)    znb4[wid][lane] = __ldcg(&z_buf4[(size_t)neg_sh[wid] * 32 + lane]);
                    else if (wid == 5) zu4[lane] = __ldcg(&z_buf4[(size_t)su_s * 32 + lane]);
                    else if (tid == 192) {
                        td_s[0] = tc - __ldg(&tb[(size_t)t * Nn]);
                        stg_node[0] = su_s;
                    }
                    if (wid == 7) {
                        unsigned balu = __ballot_sync(0xffffffffu, nb_sh[lane] == su_s);
                        if (lane == 0) { en_s = (balu == 0) ? 1u : 0u; stg_n = 1; }
                    }
                    {   // mean accumulate (pre-update reads)
                        const int i = tid & 127, r0 = (tid >> 7) * 16;
                        float a = 0.f;
#pragma unroll
                        for (int r = 0; r < 16; r++)
                            a += __ldcg(&z_buf[(size_t)nb_sh[r0 + r] * Hd + i]);
                        m_part[tid] = a;
                    }
                    __syncthreads();
                    if (tid < Hd) mean_sh[tid] = (m_part[tid] + m_part[Hd + tid]) * (1.0f / 32.0f);
                    __syncthreads();
                    if (wid < 4) matvec_part(g_Wrece4, (const float*)zu4, (float*)pbA4, wid, lane);
                    else         matvec_part(g_Wh4, mean_sh, (float*)pbB4, wid - 4, lane);
                    __syncthreads();
                    if (tid < Hd) {
                        const float* pa = (const float*)pbA4;
                        const float* pb = (const float*)pbB4;
                        float h = pa[tid] + pa[Hd + tid] + pa[2 * Hd + tid] + pa[3 * Hd + tid] + brece_s[tid]
                                + pb[tid] + pb[Hd + tid] + pb[2 * Hd + tid] + pb[3 * Hd + tid] + bh_s[tid]
                                + td_s[0] * Wt_s[tid] + bt_s[tid];
                        ((float*)stg_h4)[tid] = sigmoidf_(h);
                    }
                    if (wid < 6) {   // hawkes on pre-update embeddings (in smem)
                        const float* rowp = (wid < NEGS) ? (const float*)znb4[wid] : (const float*)zu4;
                        float a = 0.f;
#pragma unroll
                        for (int c = 0; c < 4; c++) {
                            int i = lane + 32 * c;
                            a = fmaf(rowp[i], Wo_s[i], a);
                        }
#pragma unroll
                        for (int o = 16; o > 0; o >>= 1) a += __shfl_down_sync(0xffffffffu, a, o);
                        if (lane == 0) {
                            if (wid == 5) {
                                float g = a + b_om + alpha * expf(-w_t * (tc - __ldg(&tdelta[2 * t])));
                                out[t] = psi * softplusf_(g / psi);
                            } else {
                                float tdn = tc - __ldg(&tb[(size_t)t * Nn + neg_sh[wid]]);
                                float g = a + b_om + alpha * expf(-w_t * tdn);
                                out[Bb + t * NEGS + wid] = psi * softplusf_(g / psi) * (1.0f / NEGS);
                            }
                        }
                    }
                    staged = 1;
                }
            }
            grid_barrier(gen, bid);
        }
        // flush last wave of this level, then close the level
        if (staged) {
            if (wid < stg_n && ((en_s >> wid) & 1u))
                z_buf4[(size_t)stg_node[wid] * 32 + lane] = stg_h4[wid][lane];
            staged = 0;
        }
        grid_barrier(gen, bid);
    }
}

// ---------------- launch ----------------
extern "C" void kernel_launch(void* const* d_in, const int* in_sizes, int n_in,
                              void* d_out, int out_size) {
    (void)in_sizes; (void)n_in; (void)out_size;
    const float* time_bar   = (const float*)d_in[0];
    const float* time_cur   = (const float*)d_in[1];
    const float* time_delta = (const float*)d_in[2];
    const int*   u          = (const int*)d_in[3];
    const int*   neighbors  = (const int*)d_in[4];
    const int*   neg_nodes  = (const int*)d_in[5];
    const float* z0         = (const float*)d_in[6];
    const float* W_omega    = (const float*)d_in[7];
    const float* b_omega    = (const float*)d_in[8];
    const float* W_h        = (const float*)d_in[9];
    const float* b_h        = (const float*)d_in[10];
    const float* W_e2n      = (const float*)d_in[11];
    const float* b_e2n      = (const float*)d_in[12];
    const float* W_rec_e    = (const float*)d_in[13];
    const float* b_rec_e    = (const float*)d_in[14];
    const float* W_rec_n    = (const float*)d_in[15];
    const float* b_rec_n    = (const float*)d_in[16];
    const float* W_time     = (const float*)d_in[17];
    const float* b_time     = (const float*)d_in[18];
    const float* w_t        = (const float*)d_in[19];
    const float* alpha      = (const float*)d_in[20];
    const float* psi        = (const float*)d_in[21];

    setup_kernel<<<Bb, TPB>>>(z0, u, neighbors, neg_nodes, W_h, W_e2n, W_rec_e, W_rec_n);
    levels_kernel<<<1, Bb>>>();
    dyrep_main<<<NCTA, TPB>>>(time_bar, time_cur, time_delta, u, neighbors,
                              neg_nodes, W_omega, b_omega, b_h, b_e2n, b_rec_e,
                              b_rec_n, W_time, b_time, w_t, alpha, psi,
                              (float*)d_out);
}

// round 11
// speedup vs baseline: 10.4022x; 1.2646x over previous
#include <cuda_runtime.h>
#include <math.h>

#define Nn    100000
#define Hd    128
#define Bb    512
#define Dd    32
#define NEGS  5
#define Tt    38     // touches: u + 32 nb + 5 neg
#define Ww    33     // writes:  u + 32 nb
#define NCTA  128
#define TPB   256
#define WSTEP 25     // steps per wave (step-aligned waves)
#define WPAIR 125    // pairs per wave = WSTEP*5
#define HTSZ  65536  // node hash table slots

// ---------------- device scratch ----------------
__device__ float4 z_buf4[(size_t)Nn * 32];
#define z_buf ((float*)z_buf4)
__device__ float4 g_Wh4[4096], g_We2n4[4096], g_Wrece4[4096], g_Wrecn4[4096];
__device__ unsigned long long g_ht[HTSZ];   // (node,step,flag) entries, 0 = empty
__device__ unsigned g_conf[Bb * 16];        // bitmatrix: row t2, bit t1 (t1<t2)
__device__ float g_prec[Bb * 64];           // per-step precomputed: see layout below
// layout per step t (64 floats): [0..32] td positional (0=u,1..32=nb)
//   [33..37] hawkes additive term for neg q   [38] hawkes additive for u
//   [39] en_mask (uint bits: nb j kept)       [40] en_u (uint 0/1)
__device__ int g_order[Bb];
__device__ int g_lvl_start[Bb + 1];
__device__ int g_nlv;
__device__ unsigned bar_leaf[16], bar_root, bar_gen;

__device__ __forceinline__ float sigmoidf_(float x) { return 1.0f / (1.0f + expf(-x)); }
__device__ __forceinline__ float softplusf_(float x) {
    return fmaxf(x, 0.0f) + log1pf(expf(-fabsf(x)));
}
__device__ __forceinline__ void ffma2(unsigned long long& d, unsigned long long a,
                                      unsigned long long b, unsigned long long c) {
    asm("fma.rn.f32x2 %0, %1, %2, %3;" : "=l"(d) : "l"(a), "l"(b), "l"(c));
}
__device__ __forceinline__ unsigned long long packf2(float v) {
    unsigned long long r;
    asm("mov.b64 %0, {%1, %1};" : "=l"(r) : "f"(v));
    return r;
}
__device__ __forceinline__ void unpackf2(unsigned long long p, float& lo, float& hi) {
    asm("mov.b64 {%0, %1}, %2;" : "=f"(lo), "=f"(hi) : "l"(p));
}

// tree grid barrier: 16 leaves x 8 CTAs; spinners do volatile L2 reads
__device__ __forceinline__ void grid_barrier(unsigned& gen, int bid) {
    __syncthreads();
    if (threadIdx.x == 0) {
        __threadfence();
        unsigned g = gen;
        if (atomicAdd(&bar_leaf[bid & 15], 1u) == 7u) {
            atomicExch(&bar_leaf[bid & 15], 0u);
            if (atomicAdd(&bar_root, 1u) == 15u) {
                atomicExch(&bar_root, 0u);
                __threadfence();
                atomicAdd(&bar_gen, 1u);
            }
        }
        while (*(volatile unsigned*)&bar_gen == g) {}
        gen = g + 1u;
        __threadfence();
    }
    __syncthreads();
}

// warp q of 4 covers k in [32q,32q+32) of out[i] = sum_k sv[k]*W[k*128+i]
__device__ __forceinline__ void matvec_part(const float4* __restrict__ W4,
                                            const float* __restrict__ sv,
                                            float* __restrict__ pb, int q, int lane) {
    float4 acc = make_float4(0.f, 0.f, 0.f, 0.f);
#pragma unroll
    for (int kk = 0; kk < 32; kk++) {
        int k = q * 32 + kk;
        float v = sv[k];
        float4 wv = W4[k * 32 + lane];
        acc.x = fmaf(v, wv.x, acc.x); acc.y = fmaf(v, wv.y, acc.y);
        acc.z = fmaf(v, wv.z, acc.z); acc.w = fmaf(v, wv.w, acc.w);
    }
    reinterpret_cast<float4*>(pb + q * 128)[lane] = acc;
}

// ---- 1: prep — clears, weight copies, z-row restore, per-step precompute ----
__global__ void prep_kernel(const float* __restrict__ z0,
                            const int* __restrict__ uu, const int* __restrict__ nbi,
                            const int* __restrict__ ngi,
                            const float* __restrict__ Wh, const float* __restrict__ We2n,
                            const float* __restrict__ Wrece, const float* __restrict__ Wrecn,
                            const float* __restrict__ tb, const float* __restrict__ tcur,
                            const float* __restrict__ tdelta,
                            const float* __restrict__ bomega,
                            const float* __restrict__ wt_, const float* __restrict__ alpha_) {
    __shared__ int nb_sh[Dd], su_sh;
    const int t = blockIdx.x, tid = threadIdx.x;
    const int lane = tid & 31;
    const int gidx = t * TPB + tid;

    // clears (replay determinism)
    if (gidx < HTSZ) g_ht[gidx] = 0ull;
    if (gidx < Bb * 16) g_conf[gidx] = 0u;

    // aligned weight copies (scalar loads; d_in only 4B-aligned)
    if (gidx < Hd * Hd) {
        ((float*)g_Wh4)[gidx]    = __ldg(&Wh[gidx]);
        ((float*)g_We2n4)[gidx]  = __ldg(&We2n[gidx]);
        ((float*)g_Wrece4)[gidx] = __ldg(&Wrece[gidx]);
        ((float*)g_Wrecn4)[gidx] = __ldg(&Wrecn[gidx]);
    }

    // per-step precompute (CTA = step t)
    const float tc    = __ldg(&tcur[t]);
    const float b_om  = __ldg(bomega);
    const float w_t   = __ldg(wt_);
    const float alpha = __ldg(alpha_);
    if (tid < Dd) nb_sh[tid] = __ldg(&nbi[t * Dd + tid]);
    else if (tid == Dd) su_sh = __ldg(&uu[t]);
    __syncthreads();
    if (tid < 33) {
        g_prec[t * 64 + tid] = tc - __ldg(&tb[(size_t)t * Nn + tid]);
    } else if (tid < 38) {
        int node = __ldg(&ngi[t * NEGS + tid - 33]);
        float tdn = tc - __ldg(&tb[(size_t)t * Nn + node]);
        g_prec[t * 64 + tid] = b_om + alpha * expf(-w_t * tdn);
    } else if (tid == 38) {
        float tsd = tc - __ldg(&tdelta[2 * t]);
        g_prec[t * 64 + 38] = b_om + alpha * expf(-w_t * tsd);
    }
    if (tid >= 64 && tid < 96) {  // warp 2: masks
        int j = tid - 64;
        int nbj = nb_sh[j], dup = 0;
        for (int j2 = j + 1; j2 < Dd; j2++) dup |= (nb_sh[j2] == nbj);
        unsigned bal  = __ballot_sync(0xffffffffu, !dup);
        unsigned balu = __ballot_sync(0xffffffffu, nbj == su_sh);
        if (j == 0) {
            g_prec[t * 64 + 39] = __uint_as_float(bal);
            g_prec[t * 64 + 40] = __uint_as_float(balu == 0 ? 1u : 0u);
        }
    }

    // restore touched z rows from z0 (warp per (step,touch) entry)
    int gw = gidx >> 5;
    int nw = (gridDim.x * TPB) >> 5;
    for (int e = gw; e < Bb * Tt; e += nw) {
        int tt = e / Tt, i = e - tt * Tt;
        int node = (i == 0) ? __ldg(&uu[tt])
                 : (i < Ww) ? __ldg(&nbi[tt * Dd + i - 1])
                            : __ldg(&ngi[tt * NEGS + i - Ww]);
        const float* s = z0 + (size_t)node * Hd + lane * 4;
        float4 v;
        v.x = __ldg(s); v.y = __ldg(s + 1); v.z = __ldg(s + 2); v.w = __ldg(s + 3);
        z_buf4[(size_t)node * 32 + lane] = v;
    }
}

// ---- 2: conflicts via node hash table, O(B*Tt): one thread per entry ----
// Soundness: same-node entries share the probe start; an entry can never insert
// into a slot a same-node prober already passed (passed slots were occupied by
// third entries and are never freed; an empty passed slot would have been
// claimed). Hence the later-arriving entry always CAS-fails against the earlier
// one and records the pair.
__global__ void conflict_kernel(const int* __restrict__ uu, const int* __restrict__ nbi,
                                const int* __restrict__ ngi) {
    int e = blockIdx.x * blockDim.x + threadIdx.x;
    if (e >= Bb * Tt) return;
    int step = e / Tt, i = e - step * Tt;
    int node = (i == 0) ? __ldg(&uu[step])
             : (i < Ww) ? __ldg(&nbi[step * Dd + i - 1])
                        : __ldg(&ngi[step * NEGS + i - Ww]);
    unsigned fl = (i < Ww) ? 1u : 0u;
    unsigned long long me = ((unsigned long long)node << 11)
                          | ((unsigned long long)step << 2) | (fl << 1) | 1ull;
    unsigned s = ((unsigned)node * 2654435761u) & (HTSZ - 1);
    for (;;) {
        unsigned long long old = atomicCAS(&g_ht[s], 0ull, me);
        if (old == 0ull) break;                       // inserted
        int onode = (int)(old >> 11);
        if (onode == node) {
            int ostep = (int)((old >> 2) & 511ull);
            unsigned ofl = (unsigned)((old >> 1) & 1ull);
            if (ostep != step && (fl | ofl)) {
                int t1 = min(step, ostep), t2 = max(step, ostep);
                atomicOr(&g_conf[t2 * 16 + (t1 >> 5)], 1u << (t1 & 31));
            }
        }
        s = (s + 1) & (HTSZ - 1);
    }
}

// ---- 3: exact longest-path levels, warp-serial chunks (NO spins) + sort ----
__global__ void levels_kernel() {
    __shared__ unsigned lv[Bb];
    __shared__ unsigned cnt[Bb + 1];
    __shared__ unsigned maxl;
    const int t = threadIdx.x, lane = t & 31, ch = t >> 5;
    unsigned row[16];
#pragma unroll
    for (int j = 0; j < 16; j++) row[j] = g_conf[t * 16 + j];
    if (t == 0) maxl = 0;
    __syncthreads();
    unsigned mylvl = 0;
    for (int r = 0; r < 16; r++) {
        if (ch == r) {
            unsigned m = 0;
            for (int j = 0; j < r; j++) {
                unsigned wb = row[j];
                while (wb) {
                    int b = __ffs(wb) - 1; wb &= wb - 1;
                    unsigned l = lv[j * 32 + b];
                    if (l > m) m = l;
                }
            }
            unsigned inw = row[r];
            for (int p = 0; p < 32; p++) {
                if (lane == p) mylvl = m + 1u;
                unsigned v = __shfl_sync(0xffffffffu, mylvl, p);
                if (lane > p && ((inw >> p) & 1u) && v > m) m = v;
            }
            lv[t] = mylvl;
        }
        __syncthreads();
    }
    cnt[t] = 0;
    if (t == 0) cnt[Bb] = 0;
    __syncthreads();
    atomicAdd(&cnt[mylvl], 1u);
    atomicMax(&maxl, mylvl);
    __syncthreads();
    if (t == 0) {
        unsigned s = 0, M = maxl;
        for (unsigned l = 1; l <= M; l++) {
            unsigned c = cnt[l]; cnt[l] = s; g_lvl_start[l - 1] = (int)s; s += c;
        }
        g_lvl_start[M] = Bb;
        g_nlv = (int)M;
    }
    __syncthreads();
    g_order[atomicAdd(&cnt[mylvl], 1u)] = t;
}

// ---- 4: main — 5 CTAs/step, two-phase staged writes, step-aligned waves ----
__global__ void __launch_bounds__(TPB, 1) dyrep_main(
    const int* __restrict__ uu, const int* __restrict__ nbi, const int* __restrict__ ngi,
    const float* __restrict__ Womega,
    const float* __restrict__ bh, const float* __restrict__ be2n,
    const float* __restrict__ brece, const float* __restrict__ brecn,
    const float* __restrict__ Wtime, const float* __restrict__ btime,
    const float* __restrict__ psi_, float* __restrict__ out)
{
    __shared__ int    nb_sh[Dd], su_s, neg_sh[NEGS];
    __shared__ float4 znb4[8][32];        // gemm: 8 nb rows | hub: 5 neg rows
    __shared__ float4 zu4[32];
    __shared__ float4 pbA4[4][32], pbB4[4][32];
    __shared__ float  s_sh[Hd];
    __shared__ float  m_part[2 * Hd];
    __shared__ float  mean_sh[Hd];
    __shared__ float  td_s[8];
    __shared__ unsigned en_s;
    __shared__ int    stg_n, stg_node[8];
    __shared__ float4 stg_h4[8][32];
    __shared__ float  Wo_s[Hd], Wt_s[Hd], bt_s[Hd], brn_s[Hd], be2n_s[Hd], brece_s[Hd], bh_s[Hd];

    const int tid = threadIdx.x, wid = tid >> 5, lane = tid & 31, bid = blockIdx.x;
    const float psi = __ldg(psi_);

    if (tid < Hd) {
        Wo_s[tid] = __ldg(&Womega[tid]); Wt_s[tid] = __ldg(&Wtime[tid]);
        bt_s[tid] = __ldg(&btime[tid]);  brn_s[tid] = __ldg(&brecn[tid]);
        be2n_s[tid] = __ldg(&be2n[tid]); brece_s[tid] = __ldg(&brece[tid]);
        bh_s[tid] = __ldg(&bh[tid]);
    }
    unsigned gen = 0;
    if (tid == 0) gen = *(volatile unsigned*)&bar_gen;
    __syncthreads();

    int staged = 0;
    const int nlv = g_nlv;
    for (int lvi = 0; lvi < nlv; lvi++) {
        const int s0 = g_lvl_start[lvi];
        const int w  = g_lvl_start[lvi + 1] - s0;
        const int npairs = w * 5;
        const int nwave = (w + WSTEP - 1) / WSTEP;
        for (int k = 0; k < nwave; k++) {
            if (staged) {   // phase B of previous wave (disjoint from this wave's reads)
                if (wid < stg_n && ((en_s >> wid) & 1u))
                    z_buf4[(size_t)stg_node[wid] * 32 + lane] = stg_h4[wid][lane];
                staged = 0;
            }
            __syncthreads();

            const int pi = k * WPAIR + bid;
            if (bid < WPAIR && pi < npairs) {
                const int t = g_order[s0 + pi / 5];
                const int role = pi - (pi / 5) * 5;
                const float* prec = &g_prec[t * 64];

                if (role < 4) {
                    // ===== GEMM role: rows [8*role, 8*role+8) =====
                    if (tid < Dd)       nb_sh[tid] = __ldg(&nbi[t * Dd + tid]);
                    else if (tid == Dd) su_s = __ldg(&uu[t]);
                    __syncthreads();
                    const int j0 = role * 8;
                    znb4[wid][lane] = __ldcg(&z_buf4[(size_t)nb_sh[j0 + wid] * 32 + lane]);
                    if (tid < 32) zu4[tid] = __ldcg(&z_buf4[(size_t)su_s * 32 + tid]);
                    else if (tid < 40) {
                        td_s[tid - 32] = __ldcg(&prec[1 + j0 + tid - 32]);
                        stg_node[tid - 32] = nb_sh[j0 + tid - 32];
                    } else if (tid == 40) {
                        en_s = (__float_as_uint(__ldcg(&prec[39])) >> j0) & 0xffu;
                        stg_n = 8;
                    }
                    __syncthreads();   // zu4 (warp 0) must be visible to warps 4-7
                    if (wid >= 4)  // s = z_u @ W_e2n (warps 4-7)
                        matvec_part(g_We2n4, (const float*)zu4, (float*)pbA4, wid - 4, lane);
                    __syncthreads();
                    if (tid < Hd) {
                        const float* pa = (const float*)pbA4;
                        s_sh[tid] = pa[tid] + pa[Hd + tid] + pa[2 * Hd + tid] + pa[3 * Hd + tid]
                                  + be2n_s[tid] + brn_s[tid] + bt_s[tid];
                    }
                    __syncthreads();
                    // row GEMM: warp w -> row j0+w, packed f32x2
                    unsigned long long acc01 = 0ull, acc23 = 0ull;
                    const float* zr = (const float*)znb4[wid];
                    const ulonglong2* W2 = reinterpret_cast<const ulonglong2*>(g_Wrecn4);
#pragma unroll 8
                    for (int k2 = 0; k2 < Hd; k2++) {
                        unsigned long long zz = packf2(zr[k2]);
                        ulonglong2 wv = W2[k2 * 32 + lane];
                        ffma2(acc01, zz, wv.x, acc01);
                        ffma2(acc23, zz, wv.y, acc23);
                    }
                    float ax, ay, az, aw;
                    unpackf2(acc01, ax, ay); unpackf2(acc23, az, aw);
                    const int c0 = lane * 4;
                    const float td = td_s[wid];
                    float4 h;
                    h.x = sigmoidf_(ax + s_sh[c0]     + td * Wt_s[c0]);
                    h.y = sigmoidf_(ay + s_sh[c0 + 1] + td * Wt_s[c0 + 1]);
                    h.z = sigmoidf_(az + s_sh[c0 + 2] + td * Wt_s[c0 + 2]);
                    h.w = sigmoidf_(aw + s_sh[c0 + 3] + td * Wt_s[c0 + 3]);
                    stg_h4[wid][lane] = h;
                    staged = 1;
                } else {
                    // ===== hub role: mean, W_h, W_rec_e, h_u, hawkes =====
                    if (tid < Dd)       nb_sh[tid] = __ldg(&nbi[t * Dd + tid]);
                    else if (tid == Dd) su_s = __ldg(&uu[t]);
                    else if (tid < Dd + 1 + NEGS) neg_sh[tid - 33] = __ldg(&ngi[t * NEGS + tid - 33]);
                    __syncthreads();
                    if (wid < NEGS)    znb4[wid][lane] = __ldcg(&z_buf4[(size_t)neg_sh[wid] * 32 + lane]);
                    else if (wid == 5) zu4[lane] = __ldcg(&z_buf4[(size_t)su_s * 32 + lane]);
                    else if (tid == 192) {
                        td_s[0] = __ldcg(&prec[0]);
                        stg_node[0] = su_s;
                    } else if (tid == 193) {
                        en_s = __float_as_uint(__ldcg(&prec[40]));
                        stg_n = 1;
                    }
                    {   // mean accumulate (pre-update reads)
                        const int i = tid & 127, r0 = (tid >> 7) * 16;
                        float a = 0.f;
#pragma unroll
                        for (int r = 0; r < 16; r++)
                            a += __ldcg(&z_buf[(size_t)nb_sh[r0 + r] * Hd + i]);
                        m_part[tid] = a;
                    }
                    __syncthreads();
                    if (tid < Hd) mean_sh[tid] = (m_part[tid] + m_part[Hd + tid]) * (1.0f / 32.0f);
                    __syncthreads();
                    if (wid < 4) matvec_part(g_Wrece4, (const float*)zu4, (float*)pbA4, wid, lane);
                    else         matvec_part(g_Wh4, mean_sh, (float*)pbB4, wid - 4, lane);
                    __syncthreads();
                    if (tid < Hd) {
                        const float* pa = (const float*)pbA4;
                        const float* pb = (const float*)pbB4;
                        float h = pa[tid] + pa[Hd + tid] + pa[2 * Hd + tid] + pa[3 * Hd + tid] + brece_s[tid]
                                + pb[tid] + pb[Hd + tid] + pb[2 * Hd + tid] + pb[3 * Hd + tid] + bh_s[tid]
                                + td_s[0] * Wt_s[tid] + bt_s[tid];
                        ((float*)stg_h4)[tid] = sigmoidf_(h);
                    }
                    if (wid < 6) {   // hawkes on pre-update embeddings (in smem)
                        const float* rowp = (wid < NEGS) ? (const float*)znb4[wid] : (const float*)zu4;
                        float a = 0.f;
#pragma unroll
                        for (int c = 0; c < 4; c++) {
                            int i = lane + 32 * c;
                            a = fmaf(rowp[i], Wo_s[i], a);
                        }
#pragma unroll
                        for (int o = 16; o > 0; o >>= 1) a += __shfl_down_sync(0xffffffffu, a, o);
                        if (lane == 0) {
                            float hb = __ldcg(&prec[(wid == 5) ? 38 : (33 + wid)]);
                            float g = a + hb;
                            float lamv = psi * softplusf_(g / psi);
                            if (wid == 5) out[t] = lamv;
                            else          out[Bb + t * NEGS + wid] = lamv * (1.0f / NEGS);
                        }
                    }
                    staged = 1;
                }
            }
            grid_barrier(gen, bid);
        }
        if (staged) {   // flush last wave of this level
            if (wid < stg_n && ((en_s >> wid) & 1u))
                z_buf4[(size_t)stg_node[wid] * 32 + lane] = stg_h4[wid][lane];
            staged = 0;
        }
        grid_barrier(gen, bid);
    }
}

// ---------------- launch ----------------
extern "C" void kernel_launch(void* const* d_in, const int* in_sizes, int n_in,
                              void* d_out, int out_size) {
    (void)in_sizes; (void)n_in; (void)out_size;
    const float* time_bar   = (const float*)d_in[0];
    const float* time_cur   = (const float*)d_in[1];
    const float* time_delta = (const float*)d_in[2];
    const int*   u          = (const int*)d_in[3];
    const int*   neighbors  = (const int*)d_in[4];
    const int*   neg_nodes  = (const int*)d_in[5];
    const float* z0         = (const float*)d_in[6];
    const float* W_omega    = (const float*)d_in[7];
    const float* b_omega    = (const float*)d_in[8];
    const float* W_h        = (const float*)d_in[9];
    const float* b_h        = (const float*)d_in[10];
    const float* W_e2n      = (const float*)d_in[11];
    const float* b_e2n      = (const float*)d_in[12];
    const float* W_rec_e    = (const float*)d_in[13];
    const float* b_rec_e    = (const float*)d_in[14];
    const float* W_rec_n    = (const float*)d_in[15];
    const float* b_rec_n    = (const float*)d_in[16];
    const float* W_time     = (const float*)d_in[17];
    const float* b_time     = (const float*)d_in[18];
    const float* w_t        = (const float*)d_in[19];
    const float* alpha      = (const float*)d_in[20];
    const float* psi        = (const float*)d_in[21];

    prep_kernel<<<Bb, TPB>>>(z0, u, neighbors, neg_nodes, W_h, W_e2n, W_rec_e,
                             W_rec_n, time_bar, time_cur, time_delta,
                             b_omega, w_t, alpha);
    conflict_kernel<<<(Bb * Tt + TPB - 1) / TPB, TPB>>>(u, neighbors, neg_nodes);
    levels_kernel<<<1, Bb>>>();
    dyrep_main<<<NCTA, TPB>>>(u, neighbors, neg_nodes, W_omega, b_h, b_e2n,
                              b_rec_e, b_rec_n, W_time, b_time, psi,
                              (float*)d_out);
}

// round 13
// speedup vs baseline: 13.3540x; 1.2838x over previous
#include <cuda_runtime.h>
#include <math.h>

#define Nn    100000
#define Hd    128
#define Bb    512
#define Dd    32
#define NEGS  5
#define Tt    38     // touches: u + 32 nb + 5 neg
#define Ww    33     // writes:  u + 32 nb
#define NCTA  128
#define TPB   256
#define WSTEP 25     // steps per wave (step-aligned waves)
#define WPAIR 125    // pairs per wave = WSTEP*5
#define HTSZ  65536  // node hash table slots

// ---------------- device scratch ----------------
__device__ float4 z_buf4[(size_t)Nn * 32];
#define z_buf ((float*)z_buf4)
__device__ float4 g_Wh4[4096], g_We2n4[4096], g_Wrece4[4096], g_Wrecn4[4096];
__device__ unsigned long long g_ht[HTSZ];   // (node,step,flag) entries, 0 = empty
__device__ unsigned g_conf[Bb * 16];        // bitmatrix: row t2, bit t1 (t1<t2)
__device__ float g_prec[Bb * 64];           // per-step precomputed (layout below)
// per step t (64 floats): [0..32] td positional (0=u,1..32=nb)
//   [33..37] hawkes additive for neg q   [38] hawkes additive for u
//   [39] en_mask (uint bits)             [40] en_u (uint 0/1)
__device__ int g_order[Bb];
__device__ int g_lvl_start[Bb + 1];
__device__ int g_nlv;
__device__ unsigned bar_leaf[16], bar_root, bar_gen;

__device__ __forceinline__ float sigmoidf_(float x) { return 1.0f / (1.0f + expf(-x)); }
__device__ __forceinline__ float softplusf_(float x) {
    return fmaxf(x, 0.0f) + log1pf(expf(-fabsf(x)));
}
__device__ __forceinline__ void ffma2(unsigned long long& d, unsigned long long a,
                                      unsigned long long b, unsigned long long c) {
    asm("fma.rn.f32x2 %0, %1, %2, %3;" : "=l"(d) : "l"(a), "l"(b), "l"(c));
}
__device__ __forceinline__ unsigned long long packf2(float v) {
    unsigned long long r;
    asm("mov.b64 %0, {%1, %1};" : "=l"(r) : "f"(v));
    return r;
}

// tree grid barrier: 16 leaves x 8 CTAs; spinners do volatile L2 reads
__device__ __forceinline__ void grid_barrier(unsigned& gen, int bid) {
    __syncthreads();
    if (threadIdx.x == 0) {
        __threadfence();
        unsigned g = gen;
        if (atomicAdd(&bar_leaf[bid & 15], 1u) == 7u) {
            atomicExch(&bar_leaf[bid & 15], 0u);
            if (atomicAdd(&bar_root, 1u) == 15u) {
                atomicExch(&bar_root, 0u);
                __threadfence();
                atomicAdd(&bar_gen, 1u);
            }
        }
        while (*(volatile unsigned*)&bar_gen == g) {}
        gen = g + 1u;
        __threadfence();
    }
    __syncthreads();
}

// warp q of 4 covers k in [32q,32q+32) of out[i] = sum_k sv[k]*W[k*128+i]
__device__ __forceinline__ void matvec_part(const float4* __restrict__ W4,
                                            const float* __restrict__ sv,
                                            float* __restrict__ pb, int q, int lane) {
    float4 acc = make_float4(0.f, 0.f, 0.f, 0.f);
#pragma unroll
    for (int kk = 0; kk < 32; kk++) {
        int k = q * 32 + kk;
        float v = sv[k];
        float4 wv = W4[k * 32 + lane];
        acc.x = fmaf(v, wv.x, acc.x); acc.y = fmaf(v, wv.y, acc.y);
        acc.z = fmaf(v, wv.z, acc.z); acc.w = fmaf(v, wv.w, acc.w);
    }
    reinterpret_cast<float4*>(pb + q * 128)[lane] = acc;
}

// ---- 1: prep — clears, weight copies, z-row restore, per-step precompute ----
__global__ void prep_kernel(const float* __restrict__ z0,
                            const int* __restrict__ uu, const int* __restrict__ nbi,
                            const int* __restrict__ ngi,
                            const float* __restrict__ Wh, const float* __restrict__ We2n,
                            const float* __restrict__ Wrece, const float* __restrict__ Wrecn,
                            const float* __restrict__ tb, const float* __restrict__ tcur,
                            const float* __restrict__ tdelta,
                            const float* __restrict__ bomega,
                            const float* __restrict__ wt_, const float* __restrict__ alpha_) {
    __shared__ int nb_sh[Dd], su_sh;
    const int t = blockIdx.x, tid = threadIdx.x;
    const int lane = tid & 31;
    const int gidx = t * TPB + tid;

    if (gidx < HTSZ) g_ht[gidx] = 0ull;
    if (gidx < Bb * 16) g_conf[gidx] = 0u;

    if (gidx < Hd * Hd) {
        ((float*)g_Wh4)[gidx]    = __ldg(&Wh[gidx]);
        ((float*)g_We2n4)[gidx]  = __ldg(&We2n[gidx]);
        ((float*)g_Wrece4)[gidx] = __ldg(&Wrece[gidx]);
        ((float*)g_Wrecn4)[gidx] = __ldg(&Wrecn[gidx]);
    }

    const float tc    = __ldg(&tcur[t]);
    const float b_om  = __ldg(bomega);
    const float w_t   = __ldg(wt_);
    const float alpha = __ldg(alpha_);
    if (tid < Dd) nb_sh[tid] = __ldg(&nbi[t * Dd + tid]);
    else if (tid == Dd) su_sh = __ldg(&uu[t]);
    __syncthreads();
    if (tid < 33) {
        g_prec[t * 64 + tid] = tc - __ldg(&tb[(size_t)t * Nn + tid]);
    } else if (tid < 38) {
        int node = __ldg(&ngi[t * NEGS + tid - 33]);
        float tdn = tc - __ldg(&tb[(size_t)t * Nn + node]);
        g_prec[t * 64 + tid] = b_om + alpha * expf(-w_t * tdn);
    } else if (tid == 38) {
        float tsd = tc - __ldg(&tdelta[2 * t]);
        g_prec[t * 64 + 38] = b_om + alpha * expf(-w_t * tsd);
    }
    if (tid >= 64 && tid < 96) {  // warp 2: masks
        int j = tid - 64;
        int nbj = nb_sh[j], dup = 0;
        for (int j2 = j + 1; j2 < Dd; j2++) dup |= (nb_sh[j2] == nbj);
        unsigned bal  = __ballot_sync(0xffffffffu, !dup);
        unsigned balu = __ballot_sync(0xffffffffu, nbj == su_sh);
        if (j == 0) {
            g_prec[t * 64 + 39] = __uint_as_float(bal);
            g_prec[t * 64 + 40] = __uint_as_float(balu == 0 ? 1u : 0u);
        }
    }

    int gw = gidx >> 5;
    int nw = (gridDim.x * TPB) >> 5;
    for (int e = gw; e < Bb * Tt; e += nw) {
        int tt = e / Tt, i = e - tt * Tt;
        int node = (i == 0) ? __ldg(&uu[tt])
                 : (i < Ww) ? __ldg(&nbi[tt * Dd + i - 1])
                            : __ldg(&ngi[tt * NEGS + i - Ww]);
        const float* s = z0 + (size_t)node * Hd + lane * 4;
        float4 v;
        v.x = __ldg(s); v.y = __ldg(s + 1); v.z = __ldg(s + 2); v.w = __ldg(s + 3);
        z_buf4[(size_t)node * 32 + lane] = v;
    }
}

// ---- 2: conflicts via node hash table, O(B*Tt) ----
__global__ void conflict_kernel(const int* __restrict__ uu, const int* __restrict__ nbi,
                                const int* __restrict__ ngi) {
    int e = blockIdx.x * blockDim.x + threadIdx.x;
    if (e >= Bb * Tt) return;
    int step = e / Tt, i = e - step * Tt;
    int node = (i == 0) ? __ldg(&uu[step])
             : (i < Ww) ? __ldg(&nbi[step * Dd + i - 1])
                        : __ldg(&ngi[step * NEGS + i - Ww]);
    unsigned fl = (i < Ww) ? 1u : 0u;
    unsigned long long me = ((unsigned long long)node << 11)
                          | ((unsigned long long)step << 2) | (fl << 1) | 1ull;
    unsigned s = ((unsigned)node * 2654435761u) & (HTSZ - 1);
    for (;;) {
        unsigned long long old = atomicCAS(&g_ht[s], 0ull, me);
        if (old == 0ull) break;
        int onode = (int)(old >> 11);
        if (onode == node) {
            int ostep = (int)((old >> 2) & 511ull);
            unsigned ofl = (unsigned)((old >> 1) & 1ull);
            if (ostep != step && (fl | ofl)) {
                int t1 = min(step, ostep), t2 = max(step, ostep);
                atomicOr(&g_conf[t2 * 16 + (t1 >> 5)], 1u << (t1 & 31));
            }
        }
        s = (s + 1) & (HTSZ - 1);
    }
}

// ---- 3: exact longest-path levels, warp-serial chunks (NO spins) + sort ----
__global__ void levels_kernel() {
    __shared__ unsigned lv[Bb];
    __shared__ unsigned cnt[Bb + 1];
    __shared__ unsigned maxl;
    const int t = threadIdx.x, lane = t & 31, ch = t >> 5;
    unsigned row[16];
#pragma unroll
    for (int j = 0; j < 16; j++) row[j] = g_conf[t * 16 + j];
    if (t == 0) maxl = 0;
    __syncthreads();
    unsigned mylvl = 0;
    for (int r = 0; r < 16; r++) {
        if (ch == r) {
            unsigned m = 0;
            for (int j = 0; j < r; j++) {
                unsigned wb = row[j];
                while (wb) {
                    int b = __ffs(wb) - 1; wb &= wb - 1;
                    unsigned l = lv[j * 32 + b];
                    if (l > m) m = l;
                }
            }
            unsigned inw = row[r];
            for (int p = 0; p < 32; p++) {
                if (lane == p) mylvl = m + 1u;
                unsigned v = __shfl_sync(0xffffffffu, mylvl, p);
                if (lane > p && ((inw >> p) & 1u) && v > m) m = v;
            }
            lv[t] = mylvl;
        }
        __syncthreads();
    }
    cnt[t] = 0;
    if (t == 0) cnt[Bb] = 0;
    __syncthreads();
    atomicAdd(&cnt[mylvl], 1u);
    atomicMax(&maxl, mylvl);
    __syncthreads();
    if (t == 0) {
        unsigned s = 0, M = maxl;
        for (unsigned l = 1; l <= M; l++) {
            unsigned c = cnt[l]; cnt[l] = s; g_lvl_start[l - 1] = (int)s; s += c;
        }
        g_lvl_start[M] = Bb;
        g_nlv = (int)M;
    }
    __syncthreads();
    g_order[atomicAdd(&cnt[mylvl], 1u)] = t;
}

// ---- 4: main — 5 CTAs/step, two-phase staged writes, step-aligned waves ----
__global__ void __launch_bounds__(TPB, 1) dyrep_main(
    const int* __restrict__ uu, const int* __restrict__ nbi, const int* __restrict__ ngi,
    const float* __restrict__ Womega,
    const float* __restrict__ bh, const float* __restrict__ be2n,
    const float* __restrict__ brece, const float* __restrict__ brecn,
    const float* __restrict__ Wtime, const float* __restrict__ btime,
    const float* __restrict__ psi_, float* __restrict__ out)
{
    __shared__ int    nb_sh[Dd], su_s, neg_sh[NEGS];
    __shared__ float4 znb4[8][32];        // gemm: 8 nb rows | hub: 5 neg rows
    __shared__ float4 zu4[32];
    __shared__ ulonglong2 pbG[8][8][32];  // GEMM k-split partials [warp][row][lane]
    __shared__ float4 pbA4[4][32], pbB4[4][32];
    __shared__ float  m_part[2 * Hd];
    __shared__ float  mean_sh[Hd];
    __shared__ float  td_s[8];
    __shared__ unsigned en_s;
    __shared__ int    stg_n, stg_node[8];
    __shared__ float4 stg_h4[8][32];
    __shared__ float  Wo_s[Hd], Wt_s[Hd], bt_s[Hd], brn_s[Hd], be2n_s[Hd], brece_s[Hd], bh_s[Hd];

    const int tid = threadIdx.x, wid = tid >> 5, lane = tid & 31, bid = blockIdx.x;
    const float psi = __ldg(psi_);

    if (tid < Hd) {
        Wo_s[tid] = __ldg(&Womega[tid]); Wt_s[tid] = __ldg(&Wtime[tid]);
        bt_s[tid] = __ldg(&btime[tid]);  brn_s[tid] = __ldg(&brecn[tid]);
        be2n_s[tid] = __ldg(&be2n[tid]); brece_s[tid] = __ldg(&brece[tid]);
        bh_s[tid] = __ldg(&bh[tid]);
    }
    unsigned gen = 0;
    if (tid == 0) gen = *(volatile unsigned*)&bar_gen;
    __syncthreads();

    int staged = 0;
    const int nlv = g_nlv;
    for (int lvi = 0; lvi < nlv; lvi++) {
        const int s0 = g_lvl_start[lvi];
        const int w  = g_lvl_start[lvi + 1] - s0;
        const int npairs = w * 5;
        const int nwave = (w + WSTEP - 1) / WSTEP;
        for (int k = 0; k < nwave; k++) {
            if (staged) {   // phase B of previous wave (disjoint from this wave's reads)
                if (wid < stg_n && ((en_s >> wid) & 1u))
                    z_buf4[(size_t)stg_node[wid] * 32 + lane] = stg_h4[wid][lane];
                staged = 0;
            }
            __syncthreads();

            const int pi = k * WPAIR + bid;
            if (bid < WPAIR && pi < npairs) {
                const int t = g_order[s0 + pi / 5];
                const int role = pi - (pi / 5) * 5;
                const float* prec = &g_prec[t * 64];

                if (role < 4) {
                    // ===== GEMM role: rows [8*role, 8*role+8), k-split =====
                    if (tid < Dd)       nb_sh[tid] = __ldg(&nbi[t * Dd + tid]);
                    else if (tid == Dd) su_s = __ldg(&uu[t]);
                    __syncthreads();
                    const int j0 = role * 8;
                    znb4[wid][lane] = __ldcg(&z_buf4[(size_t)nb_sh[j0 + wid] * 32 + lane]);
                    if (tid < 32) zu4[tid] = __ldcg(&z_buf4[(size_t)su_s * 32 + tid]);
                    else if (tid < 40) {
                        td_s[tid - 32] = __ldcg(&prec[1 + j0 + tid - 32]);
                        stg_node[tid - 32] = nb_sh[j0 + tid - 32];
                    } else if (tid == 40) {
                        en_s = (__float_as_uint(__ldcg(&prec[39])) >> j0) & 0xffu;
                        stg_n = 8;
                    }
                    __syncthreads();   // z rows + zu visible to all warps

                    // phase 1: rank-1 k-split GEMM. warp w covers k in [16w,16w+16),
                    // all 8 rows; W_rec_n read ONCE per CTA.
                    {
                        const float* zsh = (const float*)znb4;
                        const ulonglong2* W2 = reinterpret_cast<const ulonglong2*>(g_Wrecn4);
                        unsigned long long a01[8], a23[8];
#pragma unroll
                        for (int r = 0; r < 8; r++) { a01[r] = 0ull; a23[r] = 0ull; }
                        const int kb = wid * 16;
#pragma unroll
                        for (int kk = 0; kk < 16; kk++) {
                            const int kx = kb + kk;
                            ulonglong2 wv = W2[kx * 32 + lane];
#pragma unroll
                            for (int r = 0; r < 8; r++) {
                                unsigned long long zz = packf2(zsh[r * Hd + kx]);
                                ffma2(a01[r], zz, wv.x, a01[r]);
                                ffma2(a23[r], zz, wv.y, a23[r]);
                            }
                        }
#pragma unroll
                        for (int r = 0; r < 8; r++) {
                            pbG[wid][r][lane].x = a01[r];
                            pbG[wid][r][lane].y = a23[r];
                        }
                    }
                    __syncthreads();

                    // phase 2: warps 0-3 matvec s=z_u@We2n; warps 4-7 reduce GEMM partials
                    if (wid < 4) {
                        matvec_part(g_We2n4, (const float*)zu4, (float*)pbA4, wid, lane);
                    } else {
                        const int sbase = (tid - 128) * 2;
#pragma unroll
                        for (int ss = 0; ss < 2; ss++) {
                            const int slot = sbase + ss;
                            const int r = slot >> 5, ln = slot & 31;
                            float4 acc = make_float4(0.f, 0.f, 0.f, 0.f);
#pragma unroll
                            for (int w2 = 0; w2 < 8; w2++) {
                                float4 v = *reinterpret_cast<const float4*>(&pbG[w2][r][ln]);
                                acc.x += v.x; acc.y += v.y; acc.z += v.z; acc.w += v.w;
                            }
                            stg_h4[r][ln] = acc;   // raw GEMM result
                        }
                    }
                    __syncthreads();

                    // phase 3: combine — fold s terms (from pbA4 directly) + time feat
                    {
                        const int r = wid, ln = lane, c0 = ln * 4;
                        const float* pa = (const float*)pbA4;
                        float4 g = stg_h4[r][ln];
                        const float td = td_s[r];
                        float4 h;
                        h.x = sigmoidf_(g.x + pa[c0]     + pa[128 + c0]     + pa[256 + c0]     + pa[384 + c0]
                                        + be2n_s[c0]     + brn_s[c0]     + bt_s[c0]     + td * Wt_s[c0]);
                        h.y = sigmoidf_(g.y + pa[c0 + 1] + pa[128 + c0 + 1] + pa[256 + c0 + 1] + pa[384 + c0 + 1]
                                        + be2n_s[c0 + 1] + brn_s[c0 + 1] + bt_s[c0 + 1] + td * Wt_s[c0 + 1]);
                        h.z = sigmoidf_(g.z + pa[c0 + 2] + pa[128 + c0 + 2] + pa[256 + c0 + 2] + pa[384 + c0 + 2]
                                        + be2n_s[c0 + 2] + brn_s[c0 + 2] + bt_s[c0 + 2] + td * Wt_s[c0 + 2]);
                        h.w = sigmoidf_(g.w + pa[c0 + 3] + pa[128 + c0 + 3] + pa[256 + c0 + 3] + pa[384 + c0 + 3]
                                        + be2n_s[c0 + 3] + brn_s[c0 + 3] + bt_s[c0 + 3] + td * Wt_s[c0 + 3]);
                        __syncthreads();           // raw stg read done before overwrite
                        stg_h4[r][ln] = h;
                    }
                    staged = 1;
                } else {
                    // ===== hub role: mean, W_h, W_rec_e, h_u, hawkes (as R10) =====
                    if (tid < Dd)       nb_sh[tid] = __ldg(&nbi[t * Dd + tid]);
                    else if (tid == Dd) su_s = __ldg(&uu[t]);
                    else if (tid < Dd + 1 + NEGS) neg_sh[tid - 33] = __ldg(&ngi[t * NEGS + tid - 33]);
                    __syncthreads();
                    if (wid < NEGS)    znb4[wid][lane] = __ldcg(&z_buf4[(size_t)neg_sh[wid] * 32 + lane]);
                    else if (wid == 5) zu4[lane] = __ldcg(&z_buf4[(size_t)su_s * 32 + lane]);
                    else if (tid == 192) {
                        td_s[0] = __ldcg(&prec[0]);
                        stg_node[0] = su_s;
                    } else if (tid == 193) {
                        en_s = __float_as_uint(__ldcg(&prec[40]));
                        stg_n = 1;
                    }
                    {   // mean accumulate (pre-update reads)
                        const int i = tid & 127, r0 = (tid >> 7) * 16;
                        float a = 0.f;
#pragma unroll
                        for (int r = 0; r < 16; r++)
                            a += __ldcg(&z_buf[(size_t)nb_sh[r0 + r] * Hd + i]);
                        m_part[tid] = a;
                    }
                    __syncthreads();
                    if (tid < Hd) mean_sh[tid] = (m_part[tid] + m_part[Hd + tid]) * (1.0f / 32.0f);
                    __syncthreads();
                    if (wid < 4) matvec_part(g_Wrece4, (const float*)zu4, (float*)pbA4, wid, lane);
                    else         matvec_part(g_Wh4, mean_sh, (float*)pbB4, wid - 4, lane);
                    __syncthreads();
                    if (tid < Hd) {
                        const float* pa = (const float*)pbA4;
                        const float* pb = (const float*)pbB4;
                        float h = pa[tid] + pa[Hd + tid] + pa[2 * Hd + tid] + pa[3 * Hd + tid] + brece_s[tid]
                                + pb[tid] + pb[Hd + tid] + pb[2 * Hd + tid] + pb[3 * Hd + tid] + bh_s[tid]
                                + td_s[0] * Wt_s[tid] + bt_s[tid];
                        ((float*)stg_h4)[tid] = sigmoidf_(h);
                    }
                    if (wid < 6) {   // hawkes on pre-update embeddings (in smem)
                        const float* rowp = (wid < NEGS) ? (const float*)znb4[wid] : (const float*)zu4;
                        float a = 0.f;
#pragma unroll
                        for (int c = 0; c < 4; c++) {
                            int i = lane + 32 * c;
                            a = fmaf(rowp[i], Wo_s[i], a);
                        }
#pragma unroll
                        for (int o = 16; o > 0; o >>= 1) a += __shfl_down_sync(0xffffffffu, a, o);
                        if (lane == 0) {
                            float hb = __ldcg(&prec[(wid == 5) ? 38 : (33 + wid)]);
                            float g = a + hb;
                            float lamv = psi * softplusf_(g / psi);
                            if (wid == 5) out[t] = lamv;
                            else          out[Bb + t * NEGS + wid] = lamv * (1.0f / NEGS);
                        }
                    }
                    staged = 1;
                }
            }
            grid_barrier(gen, bid);
        }
        if (staged) {   // flush last wave of this level
            if (wid < stg_n && ((en_s >> wid) & 1u))
                z_buf4[(size_t)stg_node[wid] * 32 + lane] = stg_h4[wid][lane];
            staged = 0;
        }
        grid_barrier(gen, bid);
    }
}

// ---------------- launch ----------------
extern "C" void kernel_launch(void* const* d_in, const int* in_sizes, int n_in,
                              void* d_out, int out_size) {
    (void)in_sizes; (void)n_in; (void)out_size;
    const float* time_bar   = (const float*)d_in[0];
    const float* time_cur   = (const float*)d_in[1];
    const float* time_delta = (const float*)d_in[2];
    const int*   u          = (const int*)d_in[3];
    const int*   neighbors  = (const int*)d_in[4];
    const int*   neg_nodes  = (const int*)d_in[5];
    const float* z0         = (const float*)d_in[6];
    const float* W_omega    = (const float*)d_in[7];
    const float* b_omega    = (const float*)d_in[8];
    const float* W_h        = (const float*)d_in[9];
    const float* b_h        = (const float*)d_in[10];
    const float* W_e2n      = (const float*)d_in[11];
    const float* b_e2n      = (const float*)d_in[12];
    const float* W_rec_e    = (const float*)d_in[13];
    const float* b_rec_e    = (const float*)d_in[14];
    const float* W_rec_n    = (const float*)d_in[15];
    const float* b_rec_n    = (const float*)d_in[16];
    const float* W_time     = (const float*)d_in[17];
    const float* b_time     = (const float*)d_in[18];
    const float* w_t        = (const float*)d_in[19];
    const float* alpha      = (const float*)d_in[20];
    const float* psi        = (const float*)d_in[21];

    prep_kernel<<<Bb, TPB>>>(z0, u, neighbors, neg_nodes, W_h, W_e2n, W_rec_e,
                             W_rec_n, time_bar, time_cur, time_delta,
                             b_omega, w_t, alpha);
    conflict_kernel<<<(Bb * Tt + TPB - 1) / TPB, TPB>>>(u, neighbors, neg_nodes);
    levels_kernel<<<1, Bb>>>();
    dyrep_main<<<NCTA, TPB>>>(u, neighbors, neg_nodes, W_omega, b_h, b_e2n,
                              b_rec_e, b_rec_n, W_time, b_time, psi,
                              (float*)d_out);
}

// round 14
// speedup vs baseline: 17.0902x; 1.2798x over previous
#include <cuda_runtime.h>
#include <math.h>

#define Nn     100000
#define Hd     128
#define Bb     512
#define Dd     32
#define NEGS   5
#define Tt     38     // touches: u + 32 nb + 5 neg
#define Ww     33     // writes:  u + 32 nb
#define CSZ    5      // CTAs per cluster (= roles per step)
#define NCLUST 25
#define NCTA   125    // NCLUST * CSZ
#define TPB    256
#define HTSZ   65536

// ---------------- device scratch ----------------
__device__ float4 z_buf4[(size_t)Nn * 32];
#define z_buf ((float*)z_buf4)
__device__ float4 g_Wh4[4096], g_We2n4[4096], g_Wrece4[4096], g_Wrecn4[4096];
__device__ unsigned long long g_ht[HTSZ];
__device__ unsigned g_conf[Bb * 16];        // bitmatrix: row t2, bit t1 (t1<t2)
__device__ float g_prec[Bb * 64];           // per-step precomputed (layout below)
// per step t: [0..32] td positional; [33..37] hawkes add (neg); [38] hawkes add (u)
//   [39] en_mask (uint bits)  [40] en_u (uint 0/1)
__device__ int g_order[Bb];
__device__ int g_lvl_start[Bb + 1];
__device__ int g_nlv;
__device__ unsigned bar_leaf[NCLUST], bar_root, bar_gen;

__device__ __forceinline__ float sigmoidf_(float x) { return 1.0f / (1.0f + expf(-x)); }
__device__ __forceinline__ float softplusf_(float x) {
    return fmaxf(x, 0.0f) + log1pf(expf(-fabsf(x)));
}
__device__ __forceinline__ void ffma2(unsigned long long& d, unsigned long long a,
                                      unsigned long long b, unsigned long long c) {
    asm("fma.rn.f32x2 %0, %1, %2, %3;" : "=l"(d) : "l"(a), "l"(b), "l"(c));
}
__device__ __forceinline__ unsigned long long packf2(float v) {
    unsigned long long r;
    asm("mov.b64 %0, {%1, %1};" : "=l"(r) : "f"(v));
    return r;
}
#define CLUSTER_ARRIVE() asm volatile("barrier.cluster.arrive.aligned;" ::: "memory")
#define CLUSTER_WAIT()   asm volatile("barrier.cluster.wait.aligned;" ::: "memory")

// tree grid barrier: NCLUST leaves x CSZ CTAs; spinners use volatile L2 reads
__device__ __forceinline__ void grid_barrier(unsigned& gen, int cl) {
    __syncthreads();
    if (threadIdx.x == 0) {
        __threadfence();
        unsigned g = gen;
        if (atomicAdd(&bar_leaf[cl], 1u) == CSZ - 1) {
            atomicExch(&bar_leaf[cl], 0u);
            if (atomicAdd(&bar_root, 1u) == NCLUST - 1) {
                atomicExch(&bar_root, 0u);
                __threadfence();
                atomicAdd(&bar_gen, 1u);
            }
        }
        while (*(volatile unsigned*)&bar_gen == g) {}
        gen = g + 1u;
        __threadfence();
    }
    __syncthreads();
}

// warp q of 4 covers k in [32q,32q+32) of out[i] = sum_k sv[k]*W[k*128+i]
__device__ __forceinline__ void matvec_part(const float4* __restrict__ W4,
                                            const float* __restrict__ sv,
                                            float* __restrict__ pb, int q, int lane) {
    float4 acc = make_float4(0.f, 0.f, 0.f, 0.f);
#pragma unroll
    for (int kk = 0; kk < 32; kk++) {
        int k = q * 32 + kk;
        float v = sv[k];
        float4 wv = W4[k * 32 + lane];
        acc.x = fmaf(v, wv.x, acc.x); acc.y = fmaf(v, wv.y, acc.y);
        acc.z = fmaf(v, wv.z, acc.z); acc.w = fmaf(v, wv.w, acc.w);
    }
    reinterpret_cast<float4*>(pb + q * 128)[lane] = acc;
}

// ---- 1: prep — clears, weight copies, z-row restore, per-step precompute ----
__global__ void prep_kernel(const float* __restrict__ z0,
                            const int* __restrict__ uu, const int* __restrict__ nbi,
                            const int* __restrict__ ngi,
                            const float* __restrict__ Wh, const float* __restrict__ We2n,
                            const float* __restrict__ Wrece, const float* __restrict__ Wrecn,
                            const float* __restrict__ tb, const float* __restrict__ tcur,
                            const float* __restrict__ tdelta,
                            const float* __restrict__ bomega,
                            const float* __restrict__ wt_, const float* __restrict__ alpha_) {
    __shared__ int nb_sh[Dd], su_sh;
    const int t = blockIdx.x, tid = threadIdx.x;
    const int lane = tid & 31;
    const int gidx = t * TPB + tid;

    if (gidx < HTSZ) g_ht[gidx] = 0ull;
    if (gidx < Bb * 16) g_conf[gidx] = 0u;

    if (gidx < Hd * Hd) {
        ((float*)g_Wh4)[gidx]    = __ldg(&Wh[gidx]);
        ((float*)g_We2n4)[gidx]  = __ldg(&We2n[gidx]);
        ((float*)g_Wrece4)[gidx] = __ldg(&Wrece[gidx]);
        ((float*)g_Wrecn4)[gidx] = __ldg(&Wrecn[gidx]);
    }

    const float tc    = __ldg(&tcur[t]);
    const float b_om  = __ldg(bomega);
    const float w_t   = __ldg(wt_);
    const float alpha = __ldg(alpha_);
    if (tid < Dd) nb_sh[tid] = __ldg(&nbi[t * Dd + tid]);
    else if (tid == Dd) su_sh = __ldg(&uu[t]);
    __syncthreads();
    if (tid < 33) {
        g_prec[t * 64 + tid] = tc - __ldg(&tb[(size_t)t * Nn + tid]);
    } else if (tid < 38) {
        int node = __ldg(&ngi[t * NEGS + tid - 33]);
        float tdn = tc - __ldg(&tb[(size_t)t * Nn + node]);
        g_prec[t * 64 + tid] = b_om + alpha * expf(-w_t * tdn);
    } else if (tid == 38) {
        float tsd = tc - __ldg(&tdelta[2 * t]);
        g_prec[t * 64 + 38] = b_om + alpha * expf(-w_t * tsd);
    }
    if (tid >= 64 && tid < 96) {  // warp 2: masks
        int j = tid - 64;
        int nbj = nb_sh[j], dup = 0;
        for (int j2 = j + 1; j2 < Dd; j2++) dup |= (nb_sh[j2] == nbj);
        unsigned bal  = __ballot_sync(0xffffffffu, !dup);
        unsigned balu = __ballot_sync(0xffffffffu, nbj == su_sh);
        if (j == 0) {
            g_prec[t * 64 + 39] = __uint_as_float(bal);
            g_prec[t * 64 + 40] = __uint_as_float(balu == 0 ? 1u : 0u);
        }
    }

    int gw = gidx >> 5;
    int nw = (gridDim.x * TPB) >> 5;
    for (int e = gw; e < Bb * Tt; e += nw) {
        int tt = e / Tt, i = e - tt * Tt;
        int node = (i == 0) ? __ldg(&uu[tt])
                 : (i < Ww) ? __ldg(&nbi[tt * Dd + i - 1])
                            : __ldg(&ngi[tt * NEGS + i - Ww]);
        const float* s = z0 + (size_t)node * Hd + lane * 4;
        float4 v;
        v.x = __ldg(s); v.y = __ldg(s + 1); v.z = __ldg(s + 2); v.w = __ldg(s + 3);
        z_buf4[(size_t)node * 32 + lane] = v;
    }
}

// ---- 2: conflicts via node hash table, O(B*Tt) ----
__global__ void conflict_kernel(const int* __restrict__ uu, const int* __restrict__ nbi,
                                const int* __restrict__ ngi) {
    int e = blockIdx.x * blockDim.x + threadIdx.x;
    if (e >= Bb * Tt) return;
    int step = e / Tt, i = e - step * Tt;
    int node = (i == 0) ? __ldg(&uu[step])
             : (i < Ww) ? __ldg(&nbi[step * Dd + i - 1])
                        : __ldg(&ngi[step * NEGS + i - Ww]);
    unsigned fl = (i < Ww) ? 1u : 0u;
    unsigned long long me = ((unsigned long long)node << 11)
                          | ((unsigned long long)step << 2) | (fl << 1) | 1ull;
    unsigned s = ((unsigned)node * 2654435761u) & (HTSZ - 1);
    for (;;) {
        unsigned long long old = atomicCAS(&g_ht[s], 0ull, me);
        if (old == 0ull) break;
        int onode = (int)(old >> 11);
        if (onode == node) {
            int ostep = (int)((old >> 2) & 511ull);
            unsigned ofl = (unsigned)((old >> 1) & 1ull);
            if (ostep != step && (fl | ofl)) {
                int t1 = min(step, ostep), t2 = max(step, ostep);
                atomicOr(&g_conf[t2 * 16 + (t1 >> 5)], 1u << (t1 & 31));
            }
        }
        s = (s + 1) & (HTSZ - 1);
    }
}

// ---- 3: exact longest-path levels, warp-serial chunks (NO spins) + sort ----
__global__ void levels_kernel() {
    __shared__ unsigned lv[Bb];
    __shared__ unsigned cnt[Bb + 1];
    __shared__ unsigned maxl;
    const int t = threadIdx.x, lane = t & 31, ch = t >> 5;
    unsigned row[16];
#pragma unroll
    for (int j = 0; j < 16; j++) row[j] = g_conf[t * 16 + j];
    if (t == 0) maxl = 0;
    __syncthreads();
    unsigned mylvl = 0;
    for (int r = 0; r < 16; r++) {
        if (ch == r) {
            unsigned m = 0;
            for (int j = 0; j < r; j++) {
                unsigned wb = row[j];
                while (wb) {
                    int b = __ffs(wb) - 1; wb &= wb - 1;
                    unsigned l = lv[j * 32 + b];
                    if (l > m) m = l;
                }
            }
            unsigned inw = row[r];
            for (int p = 0; p < 32; p++) {
                if (lane == p) mylvl = m + 1u;
                unsigned v = __shfl_sync(0xffffffffu, mylvl, p);
                if (lane > p && ((inw >> p) & 1u) && v > m) m = v;
            }
            lv[t] = mylvl;
        }
        __syncthreads();
    }
    cnt[t] = 0;
    if (t == 0) cnt[Bb] = 0;
    __syncthreads();
    atomicAdd(&cnt[mylvl], 1u);
    atomicMax(&maxl, mylvl);
    __syncthreads();
    if (t == 0) {
        unsigned s = 0, M = maxl;
        for (unsigned l = 1; l <= M; l++) {
            unsigned c = cnt[l]; cnt[l] = s; g_lvl_start[l - 1] = (int)s; s += c;
        }
        g_lvl_start[M] = Bb;
        g_nlv = (int)M;
    }
    __syncthreads();
    g_order[atomicAdd(&cnt[mylvl], 1u)] = t;
}

// ---- 4: main — 1 cluster (5 CTAs) per step; split cluster barrier hides
//          the reads-done sync; grid barrier only at level boundaries ----
__global__ void __launch_bounds__(TPB, 1) __cluster_dims__(CSZ, 1, 1) dyrep_main(
    const int* __restrict__ uu, const int* __restrict__ nbi, const int* __restrict__ ngi,
    const float* __restrict__ Womega,
    const float* __restrict__ bh, const float* __restrict__ be2n,
    const float* __restrict__ brece, const float* __restrict__ brecn,
    const float* __restrict__ Wtime, const float* __restrict__ btime,
    const float* __restrict__ psi_, float* __restrict__ out)
{
    __shared__ int    nb_sh[Dd], su_s, neg_sh[NEGS];
    __shared__ float4 znb4[8][32];        // gemm: 8 nb rows | hub: 5 neg rows
    __shared__ float4 zu4[32];
    __shared__ ulonglong2 pbG[8][8][32];  // GEMM k-split partials [warp][row][lane]
    __shared__ float4 pbA4[4][32], pbB4[4][32];
    __shared__ float  m_part[2 * Hd];
    __shared__ float  mean_sh[Hd];
    __shared__ float  td_s[8];
    __shared__ unsigned en_s;
    __shared__ int    stg_node[8];
    __shared__ float4 stg_h4[8][32];      // raw GEMM results (phase2 -> phase3)
    __shared__ float  Wo_s[Hd], Wt_s[Hd], bt_s[Hd], brn_s[Hd], be2n_s[Hd], brece_s[Hd], bh_s[Hd];

    const int tid = threadIdx.x, wid = tid >> 5, lane = tid & 31, bid = blockIdx.x;
    const int cl = bid / CSZ, role = bid - cl * CSZ;
    const float psi = __ldg(psi_);

    if (tid < Hd) {
        Wo_s[tid] = __ldg(&Womega[tid]); Wt_s[tid] = __ldg(&Wtime[tid]);
        bt_s[tid] = __ldg(&btime[tid]);  brn_s[tid] = __ldg(&brecn[tid]);
        be2n_s[tid] = __ldg(&be2n[tid]); brece_s[tid] = __ldg(&brece[tid]);
        bh_s[tid] = __ldg(&bh[tid]);
    }
    unsigned gen = 0;
    if (tid == 0) gen = *(volatile unsigned*)&bar_gen;
    __syncthreads();

    const int nlv = g_nlv;
    for (int lvi = 0; lvi < nlv; lvi++) {
        const int s0 = g_lvl_start[lvi];
        const int w  = g_lvl_start[lvi + 1] - s0;
        for (int it = cl; it < w; it += NCLUST) {
            const int t = g_order[s0 + it];
            const float* prec = &g_prec[t * 64];

            if (role < 4) {
                // ===== GEMM role: rows [8*role, 8*role+8), k-split =====
                if (tid < Dd)       nb_sh[tid] = __ldg(&nbi[t * Dd + tid]);
                else if (tid == Dd) su_s = __ldg(&uu[t]);
                __syncthreads();
                const int j0 = role * 8;
                znb4[wid][lane] = __ldcg(&z_buf4[(size_t)nb_sh[j0 + wid] * 32 + lane]);
                if (tid < 32) zu4[tid] = __ldcg(&z_buf4[(size_t)su_s * 32 + tid]);
                else if (tid < 40) {
                    td_s[tid - 32] = __ldcg(&prec[1 + j0 + tid - 32]);
                    stg_node[tid - 32] = nb_sh[j0 + tid - 32];
                } else if (tid == 40) {
                    en_s = (__float_as_uint(__ldcg(&prec[39])) >> j0) & 0xffu;
                }
                __syncthreads();        // all pre-update reads captured in smem
                CLUSTER_ARRIVE();       // signal: my reads done

                // phase 1: rank-1 k-split GEMM; W_rec_n read ONCE per CTA
                {
                    const float* zsh = (const float*)znb4;
                    const ulonglong2* W2 = reinterpret_cast<const ulonglong2*>(g_Wrecn4);
                    unsigned long long a01[8], a23[8];
#pragma unroll
                    for (int r = 0; r < 8; r++) { a01[r] = 0ull; a23[r] = 0ull; }
                    const int kb = wid * 16;
#pragma unroll
                    for (int kk = 0; kk < 16; kk++) {
                        const int kx = kb + kk;
                        ulonglong2 wv = W2[kx * 32 + lane];
#pragma unroll
                        for (int r = 0; r < 8; r++) {
                            unsigned long long zz = packf2(zsh[r * Hd + kx]);
                            ffma2(a01[r], zz, wv.x, a01[r]);
                            ffma2(a23[r], zz, wv.y, a23[r]);
                        }
                    }
#pragma unroll
                    for (int r = 0; r < 8; r++) {
                        pbG[wid][r][lane].x = a01[r];
                        pbG[wid][r][lane].y = a23[r];
                    }
                }
                __syncthreads();

                // phase 2: warps 0-3 matvec s=z_u@We2n; warps 4-7 reduce partials
                if (wid < 4) {
                    matvec_part(g_We2n4, (const float*)zu4, (float*)pbA4, wid, lane);
                } else {
                    const int sbase = (tid - 128) * 2;
#pragma unroll
                    for (int ss = 0; ss < 2; ss++) {
                        const int slot = sbase + ss;
                        const int r = slot >> 5, ln = slot & 31;
                        float4 acc = make_float4(0.f, 0.f, 0.f, 0.f);
#pragma unroll
                        for (int w2 = 0; w2 < 8; w2++) {
                            float4 v = *reinterpret_cast<const float4*>(&pbG[w2][r][ln]);
                            acc.x += v.x; acc.y += v.y; acc.z += v.z; acc.w += v.w;
                        }
                        stg_h4[r][ln] = acc;
                    }
                }
                __syncthreads();

                // phase 3: combine into registers (flush mapping = compute mapping)
                const int c0 = lane * 4;
                const float* pa = (const float*)pbA4;
                const float4 g4 = stg_h4[wid][lane];
                const float td = td_s[wid];
                float4 h;
                h.x = sigmoidf_(g4.x + pa[c0]     + pa[128 + c0]     + pa[256 + c0]     + pa[384 + c0]
                                + be2n_s[c0]     + brn_s[c0]     + bt_s[c0]     + td * Wt_s[c0]);
                h.y = sigmoidf_(g4.y + pa[c0 + 1] + pa[128 + c0 + 1] + pa[256 + c0 + 1] + pa[384 + c0 + 1]
                                + be2n_s[c0 + 1] + brn_s[c0 + 1] + bt_s[c0 + 1] + td * Wt_s[c0 + 1]);
                h.z = sigmoidf_(g4.z + pa[c0 + 2] + pa[128 + c0 + 2] + pa[256 + c0 + 2] + pa[384 + c0 + 2]
                                + be2n_s[c0 + 2] + brn_s[c0 + 2] + bt_s[c0 + 2] + td * Wt_s[c0 + 2]);
                h.w = sigmoidf_(g4.w + pa[c0 + 3] + pa[128 + c0 + 3] + pa[256 + c0 + 3] + pa[384 + c0 + 3]
                                + be2n_s[c0 + 3] + brn_s[c0 + 3] + bt_s[c0 + 3] + td * Wt_s[c0 + 3]);
                const int node_r = stg_node[wid];     // snapshot before next-iter smem reuse
                const unsigned en_r = en_s;

                CLUSTER_WAIT();         // all 5 roles' reads done -> safe to write
                if ((en_r >> wid) & 1u)
                    z_buf4[(size_t)node_r * 32 + lane] = h;
            } else {
                // ===== hub role: mean, W_h, W_rec_e, h_u, hawkes =====
                if (tid < Dd)       nb_sh[tid] = __ldg(&nbi[t * Dd + tid]);
                else if (tid == Dd) su_s = __ldg(&uu[t]);
                else if (tid < Dd + 1 + NEGS) neg_sh[tid - 33] = __ldg(&ngi[t * NEGS + tid - 33]);
                __syncthreads();
                if (wid < NEGS)    znb4[wid][lane] = __ldcg(&z_buf4[(size_t)neg_sh[wid] * 32 + lane]);
                else if (wid == 5) zu4[lane] = __ldcg(&z_buf4[(size_t)su_s * 32 + lane]);
                else if (tid == 192) td_s[0] = __ldcg(&prec[0]);
                else if (tid == 193) en_s = __float_as_uint(__ldcg(&prec[40]));
                {   // mean accumulate (pre-update reads)
                    const int i = tid & 127, r0 = (tid >> 7) * 16;
                    float a = 0.f;
#pragma unroll
                    for (int r = 0; r < 16; r++)
                        a += __ldcg(&z_buf[(size_t)nb_sh[r0 + r] * Hd + i]);
                    m_part[tid] = a;
                }
                __syncthreads();        // all pre-update reads captured
                CLUSTER_ARRIVE();

                const int su_r = su_s;          // snapshots (smem reused next iter)
                if (tid < Hd) mean_sh[tid] = (m_part[tid] + m_part[Hd + tid]) * (1.0f / 32.0f);
                __syncthreads();
                const unsigned en_r = en_s;
                if (wid < 4) matvec_part(g_Wrece4, (const float*)zu4, (float*)pbA4, wid, lane);
                else         matvec_part(g_Wh4, mean_sh, (float*)pbB4, wid - 4, lane);
                __syncthreads();
                float hval = 0.f;
                if (tid < Hd) {
                    const float* pa = (const float*)pbA4;
                    const float* pb = (const float*)pbB4;
                    float hh = pa[tid] + pa[Hd + tid] + pa[2 * Hd + tid] + pa[3 * Hd + tid] + brece_s[tid]
                             + pb[tid] + pb[Hd + tid] + pb[2 * Hd + tid] + pb[3 * Hd + tid] + bh_s[tid]
                             + td_s[0] * Wt_s[tid] + bt_s[tid];
                    hval = sigmoidf_(hh);
                }
                if (wid < 6) {   // hawkes on pre-update embeddings (in smem)
                    const float* rowp = (wid < NEGS) ? (const float*)znb4[wid] : (const float*)zu4;
                    float a = 0.f;
#pragma unroll
                    for (int c = 0; c < 4; c++) {
                        int i = lane + 32 * c;
                        a = fmaf(rowp[i], Wo_s[i], a);
                    }
#pragma unroll
                    for (int o = 16; o > 0; o >>= 1) a += __shfl_down_sync(0xffffffffu, a, o);
                    if (lane == 0) {
                        float hb = __ldcg(&prec[(wid == 5) ? 38 : (33 + wid)]);
                        float lamv = psi * softplusf_((a + hb) / psi);
                        if (wid == 5) out[t] = lamv;
                        else          out[Bb + t * NEGS + wid] = lamv * (1.0f / NEGS);
                    }
                }

                CLUSTER_WAIT();
                if (en_r && tid < Hd)
                    z_buf[(size_t)su_r * Hd + tid] = hval;
            }
        }
        grid_barrier(gen, cl);   // level boundary: all flushes visible
    }
}

// ---------------- launch ----------------
extern "C" void kernel_launch(void* const* d_in, const int* in_sizes, int n_in,
                              void* d_out, int out_size) {
    (void)in_sizes; (void)n_in; (void)out_size;
    const float* time_bar   = (const float*)d_in[0];
    const float* time_cur   = (const float*)d_in[1];
    const float* time_delta = (const float*)d_in[2];
    const int*   u          = (const int*)d_in[3];
    const int*   neighbors  = (const int*)d_in[4];
    const int*   neg_nodes  = (const int*)d_in[5];
    const float* z0         = (const float*)d_in[6];
    const float* W_omega    = (const float*)d_in[7];
    const float* b_omega    = (const float*)d_in[8];
    const float* W_h        = (const float*)d_in[9];
    const float* b_h        = (const float*)d_in[10];
    const float* W_e2n      = (const float*)d_in[11];
    const float* b_e2n      = (const float*)d_in[12];
    const float* W_rec_e    = (const float*)d_in[13];
    const float* b_rec_e    = (const float*)d_in[14];
    const float* W_rec_n    = (const float*)d_in[15];
    const float* b_rec_n    = (const float*)d_in[16];
    const float* W_time     = (const float*)d_in[17];
    const float* b_time     = (const float*)d_in[18];
    const float* w_t        = (const float*)d_in[19];
    const float* alpha      = (const float*)d_in[20];
    const float* psi        = (const float*)d_in[21];

    prep_kernel<<<Bb, TPB>>>(z0, u, neighbors, neg_nodes, W_h, W_e2n, W_rec_e,
                             W_rec_n, time_bar, time_cur, time_delta,
                             b_omega, w_t, alpha);
    conflict_kernel<<<(Bb * Tt + TPB - 1) / TPB, TPB>>>(u, neighbors, neg_nodes);
    levels_kernel<<<1, Bb>>>();
    dyrep_main<<<NCTA, TPB>>>(u, neighbors, neg_nodes, W_omega, b_h, b_e2n,
                              b_rec_e, b_rec_n, W_time, b_time, psi,
                              (float*)d_out);
}

// round 15
// speedup vs baseline: 19.2585x; 1.1269x over previous
#include <cuda_runtime.h>
#include <math.h>

#define Nn     100000
#define Hd     128
#define Bb     512
#define Dd     32
#define NEGS   5
#define Tt     38     // touches: u + 32 nb + 5 neg
#define Ww     33     // writes:  u + 32 nb
#define CSZ    5      // CTAs per cluster (= roles per step)
#define NCLUST 25
#define NCTA   125    // NCLUST * CSZ
#define TPB    256
#define HTSZ   65536

// ---------------- device scratch ----------------
__device__ float4 z_buf4[(size_t)Nn * 32];
#define z_buf ((float*)z_buf4)
__device__ float4 g_Wh4[4096], g_We2n4[4096], g_Wrece4[4096], g_Wrecn4[4096];
__device__ unsigned long long g_ht[HTSZ];
__device__ unsigned g_conf[Bb * 16];        // bitmatrix: row t2, bit t1 (t1<t2)
__device__ float g_prec[Bb * 64];           // per-step precomputed (layout below)
// per step t: [0..32] td positional; [33..37] hawkes add (neg); [38] hawkes add (u)
//   [39] en_mask (uint bits)  [40] en_u (uint 0/1)
__device__ int g_order[Bb];
__device__ int g_lvl_start[Bb + 1];
__device__ int g_nlv;
__device__ int g_done[Bb];                  // per-step completion counter (0..5)

__device__ __forceinline__ float sigmoidf_(float x) { return 1.0f / (1.0f + expf(-x)); }
__device__ __forceinline__ float softplusf_(float x) {
    return fmaxf(x, 0.0f) + log1pf(expf(-fabsf(x)));
}
__device__ __forceinline__ void ffma2(unsigned long long& d, unsigned long long a,
                                      unsigned long long b, unsigned long long c) {
    asm("fma.rn.f32x2 %0, %1, %2, %3;" : "=l"(d) : "l"(a), "l"(b), "l"(c));
}
__device__ __forceinline__ unsigned long long packf2(float v) {
    unsigned long long r;
    asm("mov.b64 %0, {%1, %1};" : "=l"(r) : "f"(v));
    return r;
}
#define CLUSTER_ARRIVE() asm volatile("barrier.cluster.arrive.aligned;" ::: "memory")
#define CLUSTER_WAIT()   asm volatile("barrier.cluster.wait.aligned;" ::: "memory")

// warp q of 4 covers k in [32q,32q+32) of out[i] = sum_k sv[k]*W[k*128+i]
__device__ __forceinline__ void matvec_part(const float4* __restrict__ W4,
                                            const float* __restrict__ sv,
                                            float* __restrict__ pb, int q, int lane) {
    float4 acc = make_float4(0.f, 0.f, 0.f, 0.f);
#pragma unroll
    for (int kk = 0; kk < 32; kk++) {
        int k = q * 32 + kk;
        float v = sv[k];
        float4 wv = W4[k * 32 + lane];
        acc.x = fmaf(v, wv.x, acc.x); acc.y = fmaf(v, wv.y, acc.y);
        acc.z = fmaf(v, wv.z, acc.z); acc.w = fmaf(v, wv.w, acc.w);
    }
    reinterpret_cast<float4*>(pb + q * 128)[lane] = acc;
}

// ---- 1: prep — clears, weight copies, z-row restore, per-step precompute ----
__global__ void prep_kernel(const float* __restrict__ z0,
                            const int* __restrict__ uu, const int* __restrict__ nbi,
                            const int* __restrict__ ngi,
                            const float* __restrict__ Wh, const float* __restrict__ We2n,
                            const float* __restrict__ Wrece, const float* __restrict__ Wrecn,
                            const float* __restrict__ tb, const float* __restrict__ tcur,
                            const float* __restrict__ tdelta,
                            const float* __restrict__ bomega,
                            const float* __restrict__ wt_, const float* __restrict__ alpha_) {
    __shared__ int nb_sh[Dd], su_sh;
    const int t = blockIdx.x, tid = threadIdx.x;
    const int lane = tid & 31;
    const int gidx = t * TPB + tid;

    if (gidx < HTSZ) g_ht[gidx] = 0ull;
    if (gidx < Bb * 16) g_conf[gidx] = 0u;
    if (gidx < Bb) g_done[gidx] = 0;

    if (gidx < Hd * Hd) {
        ((float*)g_Wh4)[gidx]    = __ldg(&Wh[gidx]);
        ((float*)g_We2n4)[gidx]  = __ldg(&We2n[gidx]);
        ((float*)g_Wrece4)[gidx] = __ldg(&Wrece[gidx]);
        ((float*)g_Wrecn4)[gidx] = __ldg(&Wrecn[gidx]);
    }

    const float tc    = __ldg(&tcur[t]);
    const float b_om  = __ldg(bomega);
    const float w_t   = __ldg(wt_);
    const float alpha = __ldg(alpha_);
    if (tid < Dd) nb_sh[tid] = __ldg(&nbi[t * Dd + tid]);
    else if (tid == Dd) su_sh = __ldg(&uu[t]);
    __syncthreads();
    if (tid < 33) {
        g_prec[t * 64 + tid] = tc - __ldg(&tb[(size_t)t * Nn + tid]);
    } else if (tid < 38) {
        int node = __ldg(&ngi[t * NEGS + tid - 33]);
        float tdn = tc - __ldg(&tb[(size_t)t * Nn + node]);
        g_prec[t * 64 + tid] = b_om + alpha * expf(-w_t * tdn);
    } else if (tid == 38) {
        float tsd = tc - __ldg(&tdelta[2 * t]);
        g_prec[t * 64 + 38] = b_om + alpha * expf(-w_t * tsd);
    }
    if (tid >= 64 && tid < 96) {  // warp 2: masks
        int j = tid - 64;
        int nbj = nb_sh[j], dup = 0;
        for (int j2 = j + 1; j2 < Dd; j2++) dup |= (nb_sh[j2] == nbj);
        unsigned bal  = __ballot_sync(0xffffffffu, !dup);
        unsigned balu = __ballot_sync(0xffffffffu, nbj == su_sh);
        if (j == 0) {
            g_prec[t * 64 + 39] = __uint_as_float(bal);
            g_prec[t * 64 + 40] = __uint_as_float(balu == 0 ? 1u : 0u);
        }
    }

    int gw = gidx >> 5;
    int nw = (gridDim.x * TPB) >> 5;
    for (int e = gw; e < Bb * Tt; e += nw) {
        int tt = e / Tt, i = e - tt * Tt;
        int node = (i == 0) ? __ldg(&uu[tt])
                 : (i < Ww) ? __ldg(&nbi[tt * Dd + i - 1])
                            : __ldg(&ngi[tt * NEGS + i - Ww]);
        const float* s = z0 + (size_t)node * Hd + lane * 4;
        float4 v;
        v.x = __ldg(s); v.y = __ldg(s + 1); v.z = __ldg(s + 2); v.w = __ldg(s + 3);
        z_buf4[(size_t)node * 32 + lane] = v;
    }
}

// ---- 2: conflicts via node hash table, O(B*Tt) ----
__global__ void conflict_kernel(const int* __restrict__ uu, const int* __restrict__ nbi,
                                const int* __restrict__ ngi) {
    int e = blockIdx.x * blockDim.x + threadIdx.x;
    if (e >= Bb * Tt) return;
    int step = e / Tt, i = e - step * Tt;
    int node = (i == 0) ? __ldg(&uu[step])
             : (i < Ww) ? __ldg(&nbi[step * Dd + i - 1])
                        : __ldg(&ngi[step * NEGS + i - Ww]);
    unsigned fl = (i < Ww) ? 1u : 0u;
    unsigned long long me = ((unsigned long long)node << 11)
                          | ((unsigned long long)step << 2) | (fl << 1) | 1ull;
    unsigned s = ((unsigned)node * 2654435761u) & (HTSZ - 1);
    for (;;) {
        unsigned long long old = atomicCAS(&g_ht[s], 0ull, me);
        if (old == 0ull) break;
        int onode = (int)(old >> 11);
        if (onode == node) {
            int ostep = (int)((old >> 2) & 511ull);
            unsigned ofl = (unsigned)((old >> 1) & 1ull);
            if (ostep != step && (fl | ofl)) {
                int t1 = min(step, ostep), t2 = max(step, ostep);
                atomicOr(&g_conf[t2 * 16 + (t1 >> 5)], 1u << (t1 & 31));
            }
        }
        s = (s + 1) & (HTSZ - 1);
    }
}

// ---- 3: exact longest-path levels, warp-serial chunks (NO spins) + sort ----
// g_order is level-sorted: every pred of a step appears strictly earlier.
__global__ void levels_kernel() {
    __shared__ unsigned lv[Bb];
    __shared__ unsigned cnt[Bb + 1];
    __shared__ unsigned maxl;
    const int t = threadIdx.x, lane = t & 31, ch = t >> 5;
    unsigned row[16];
#pragma unroll
    for (int j = 0; j < 16; j++) row[j] = g_conf[t * 16 + j];
    if (t == 0) maxl = 0;
    __syncthreads();
    unsigned mylvl = 0;
    for (int r = 0; r < 16; r++) {
        if (ch == r) {
            unsigned m = 0;
            for (int j = 0; j < r; j++) {
                unsigned wb = row[j];
                while (wb) {
                    int b = __ffs(wb) - 1; wb &= wb - 1;
                    unsigned l = lv[j * 32 + b];
                    if (l > m) m = l;
                }
            }
            unsigned inw = row[r];
            for (int p = 0; p < 32; p++) {
                if (lane == p) mylvl = m + 1u;
                unsigned v = __shfl_sync(0xffffffffu, mylvl, p);
                if (lane > p && ((inw >> p) & 1u) && v > m) m = v;
            }
            lv[t] = mylvl;
        }
        __syncthreads();
    }
    cnt[t] = 0;
    if (t == 0) cnt[Bb] = 0;
    __syncthreads();
    atomicAdd(&cnt[mylvl], 1u);
    atomicMax(&maxl, mylvl);
    __syncthreads();
    if (t == 0) {
        unsigned s = 0, M = maxl;
        for (unsigned l = 1; l <= M; l++) {
            unsigned c = cnt[l]; cnt[l] = s; g_lvl_start[l - 1] = (int)s; s += c;
        }
        g_lvl_start[M] = Bb;
        g_nlv = (int)M;
    }
    __syncthreads();
    g_order[atomicAdd(&cnt[mylvl], 1u)] = t;
}

// ---- 4: main — 1 cluster per step, per-step DATAFLOW (no grid barriers).
// Deadlock-free: wait edges (pred pos < my pos) and per-cluster serialization
// (pos -> pos+NCLUST) both strictly increase g_order position => DAG; all 125
// CTAs co-resident => progress.
__global__ void __launch_bounds__(TPB, 1) __cluster_dims__(CSZ, 1, 1) dyrep_main(
    const int* __restrict__ uu, const int* __restrict__ nbi, const int* __restrict__ ngi,
    const float* __restrict__ Womega,
    const float* __restrict__ bh, const float* __restrict__ be2n,
    const float* __restrict__ brece, const float* __restrict__ brecn,
    const float* __restrict__ Wtime, const float* __restrict__ btime,
    const float* __restrict__ psi_, float* __restrict__ out)
{
    __shared__ int    nb_sh[Dd], su_s, neg_sh[NEGS];
    __shared__ float4 znb4[8][32];        // gemm: 8 nb rows | hub: 5 neg rows
    __shared__ float4 zu4[32];
    __shared__ ulonglong2 pbG[8][8][32];  // GEMM k-split partials [warp][row][lane]
    __shared__ float4 pbA4[4][32], pbB4[4][32];
    __shared__ float  m_part[2 * Hd];
    __shared__ float  mean_sh[Hd];
    __shared__ float  td_s[8];
    __shared__ unsigned en_s;
    __shared__ int    stg_node[8];
    __shared__ float4 stg_h4[8][32];      // raw GEMM results (phase2 -> phase3)
    __shared__ float  Wo_s[Hd], Wt_s[Hd], bt_s[Hd], brn_s[Hd], be2n_s[Hd], brece_s[Hd], bh_s[Hd];

    const int tid = threadIdx.x, wid = tid >> 5, lane = tid & 31, bid = blockIdx.x;
    const int cl = bid / CSZ, role = bid - cl * CSZ;
    const float psi = __ldg(psi_);

    if (tid < Hd) {
        Wo_s[tid] = __ldg(&Womega[tid]); Wt_s[tid] = __ldg(&Wtime[tid]);
        bt_s[tid] = __ldg(&btime[tid]);  brn_s[tid] = __ldg(&brecn[tid]);
        be2n_s[tid] = __ldg(&be2n[tid]); brece_s[tid] = __ldg(&brece[tid]);
        bh_s[tid] = __ldg(&bh[tid]);
    }
    __syncthreads();

    for (int i = cl; i < Bb; i += NCLUST) {
        const int t = g_order[i];
        const float* prec = &g_prec[t * 64];

        // ---- dataflow wait: all conflicting predecessors fully done ----
        if (tid < 32) {
#pragma unroll
            for (int j = 0; j < 16; j++) {
                unsigned wb = __ldcg(&g_conf[t * 16 + j]);
                if ((wb >> lane) & 1u) {
                    int p = j * 32 + lane;
                    while (*(volatile int*)&g_done[p] != CSZ) {}
                }
            }
            __threadfence();
        }
        __syncthreads();

        if (role < 4) {
            // ===== GEMM role: rows [8*role, 8*role+8), k-split =====
            if (tid < Dd)       nb_sh[tid] = __ldg(&nbi[t * Dd + tid]);
            else if (tid == Dd) su_s = __ldg(&uu[t]);
            __syncthreads();
            const int j0 = role * 8;
            znb4[wid][lane] = __ldcg(&z_buf4[(size_t)nb_sh[j0 + wid] * 32 + lane]);
            if (tid < 32) zu4[tid] = __ldcg(&z_buf4[(size_t)su_s * 32 + tid]);
            else if (tid < 40) {
                td_s[tid - 32] = __ldcg(&prec[1 + j0 + tid - 32]);
                stg_node[tid - 32] = nb_sh[j0 + tid - 32];
            } else if (tid == 40) {
                en_s = (__float_as_uint(__ldcg(&prec[39])) >> j0) & 0xffu;
            }
            __syncthreads();        // all pre-update reads captured in smem
            CLUSTER_ARRIVE();       // signal: my reads done

            // phase 1: rank-1 k-split GEMM; W_rec_n read ONCE per CTA
            {
                const float* zsh = (const float*)znb4;
                const ulonglong2* W2 = reinterpret_cast<const ulonglong2*>(g_Wrecn4);
                unsigned long long a01[8], a23[8];
#pragma unroll
                for (int r = 0; r < 8; r++) { a01[r] = 0ull; a23[r] = 0ull; }
                const int kb = wid * 16;
#pragma unroll
                for (int kk = 0; kk < 16; kk++) {
                    const int kx = kb + kk;
                    ulonglong2 wv = W2[kx * 32 + lane];
#pragma unroll
                    for (int r = 0; r < 8; r++) {
                        unsigned long long zz = packf2(zsh[r * Hd + kx]);
                        ffma2(a01[r], zz, wv.x, a01[r]);
                        ffma2(a23[r], zz, wv.y, a23[r]);
                    }
                }
#pragma unroll
                for (int r = 0; r < 8; r++) {
                    pbG[wid][r][lane].x = a01[r];
                    pbG[wid][r][lane].y = a23[r];
                }
            }
            __syncthreads();

            // phase 2: warps 0-3 matvec s=z_u@We2n; warps 4-7 reduce partials
            if (wid < 4) {
                matvec_part(g_We2n4, (const float*)zu4, (float*)pbA4, wid, lane);
            } else {
                const int sbase = (tid - 128) * 2;
#pragma unroll
                for (int ss = 0; ss < 2; ss++) {
                    const int slot = sbase + ss;
                    const int r = slot >> 5, ln = slot & 31;
                    float4 acc = make_float4(0.f, 0.f, 0.f, 0.f);
#pragma unroll
                    for (int w2 = 0; w2 < 8; w2++) {
                        float4 v = *reinterpret_cast<const float4*>(&pbG[w2][r][ln]);
                        acc.x += v.x; acc.y += v.y; acc.z += v.z; acc.w += v.w;
                    }
                    stg_h4[r][ln] = acc;
                }
            }
            __syncthreads();

            // phase 3: combine into registers (flush mapping = compute mapping)
            const int c0 = lane * 4;
            const float* pa = (const float*)pbA4;
            const float4 g4 = stg_h4[wid][lane];
            const float td = td_s[wid];
            float4 h;
            h.x = sigmoidf_(g4.x + pa[c0]     + pa[128 + c0]     + pa[256 + c0]     + pa[384 + c0]
                            + be2n_s[c0]     + brn_s[c0]     + bt_s[c0]     + td * Wt_s[c0]);
            h.y = sigmoidf_(g4.y + pa[c0 + 1] + pa[128 + c0 + 1] + pa[256 + c0 + 1] + pa[384 + c0 + 1]
                            + be2n_s[c0 + 1] + brn_s[c0 + 1] + bt_s[c0 + 1] + td * Wt_s[c0 + 1]);
            h.z = sigmoidf_(g4.z + pa[c0 + 2] + pa[128 + c0 + 2] + pa[256 + c0 + 2] + pa[384 + c0 + 2]
                            + be2n_s[c0 + 2] + brn_s[c0 + 2] + bt_s[c0 + 2] + td * Wt_s[c0 + 2]);
            h.w = sigmoidf_(g4.w + pa[c0 + 3] + pa[128 + c0 + 3] + pa[256 + c0 + 3] + pa[384 + c0 + 3]
                            + be2n_s[c0 + 3] + brn_s[c0 + 3] + bt_s[c0 + 3] + td * Wt_s[c0 + 3]);
            const int node_r = stg_node[wid];     // snapshot before next-iter smem reuse
            const unsigned en_r = en_s;

            CLUSTER_WAIT();         // all 5 roles' reads done -> safe to write
            if ((en_r >> wid) & 1u)
                z_buf4[(size_t)node_r * 32 + lane] = h;
        } else {
            // ===== hub role: mean, W_h, W_rec_e, h_u, hawkes =====
            if (tid < Dd)       nb_sh[tid] = __ldg(&nbi[t * Dd + tid]);
            else if (tid == Dd) su_s = __ldg(&uu[t]);
            else if (tid < Dd + 1 + NEGS) neg_sh[tid - 33] = __ldg(&ngi[t * NEGS + tid - 33]);
            __syncthreads();
            if (wid < NEGS)    znb4[wid][lane] = __ldcg(&z_buf4[(size_t)neg_sh[wid] * 32 + lane]);
            else if (wid == 5) zu4[lane] = __ldcg(&z_buf4[(size_t)su_s * 32 + lane]);
            else if (tid == 192) td_s[0] = __ldcg(&prec[0]);
            else if (tid == 193) en_s = __float_as_uint(__ldcg(&prec[40]));
            {   // mean accumulate (pre-update reads)
                const int i2 = tid & 127, r0 = (tid >> 7) * 16;
                float a = 0.f;
#pragma unroll
                for (int r = 0; r < 16; r++)
                    a += __ldcg(&z_buf[(size_t)nb_sh[r0 + r] * Hd + i2]);
                m_part[tid] = a;
            }
            __syncthreads();        // all pre-update reads captured
            CLUSTER_ARRIVE();

            const int su_r = su_s;          // snapshots (smem reused next iter)
            if (tid < Hd) mean_sh[tid] = (m_part[tid] + m_part[Hd + tid]) * (1.0f / 32.0f);
            __syncthreads();
            const unsigned en_r = en_s;
            if (wid < 4) matvec_part(g_Wrece4, (const float*)zu4, (float*)pbA4, wid, lane);
            else         matvec_part(g_Wh4, mean_sh, (float*)pbB4, wid - 4, lane);
            __syncthreads();
            float hval = 0.f;
            if (tid < Hd) {
                const float* pa = (const float*)pbA4;
                const float* pb = (const float*)pbB4;
                float hh = pa[tid] + pa[Hd + tid] + pa[2 * Hd + tid] + pa[3 * Hd + tid] + brece_s[tid]
                         + pb[tid] + pb[Hd + tid] + pb[2 * Hd + tid] + pb[3 * Hd + tid] + bh_s[tid]
                         + td_s[0] * Wt_s[tid] + bt_s[tid];
                hval = sigmoidf_(hh);
            }
            if (wid < 6) {   // hawkes on pre-update embeddings (in smem)
                const float* rowp = (wid < NEGS) ? (const float*)znb4[wid] : (const float*)zu4;
                float a = 0.f;
#pragma unroll
                for (int c = 0; c < 4; c++) {
                    int i2 = lane + 32 * c;
                    a = fmaf(rowp[i2], Wo_s[i2], a);
                }
#pragma unroll
                for (int o = 16; o > 0; o >>= 1) a += __shfl_down_sync(0xffffffffu, a, o);
                if (lane == 0) {
                    float hb = __ldcg(&prec[(wid == 5) ? 38 : (33 + wid)]);
                    float lamv = psi * softplusf_((a + hb) / psi);
                    if (wid == 5) out[t] = lamv;
                    else          out[Bb + t * NEGS + wid] = lamv * (1.0f / NEGS);
                }
            }

            CLUSTER_WAIT();
            if (en_r && tid < Hd)
                z_buf[(size_t)su_r * Hd + tid] = hval;
        }

        // ---- signal: this role's writes are globally visible ----
        __syncthreads();                     // all warps' stores ordered before fence
        if (tid == 0) {
            __threadfence();                 // cumulative: publishes whole CTA's writes
            atomicAdd(&g_done[t], 1);
        }
    }
}

// ---------------- launch ----------------
extern "C" void kernel_launch(void* const* d_in, const int* in_sizes, int n_in,
                              void* d_out, int out_size) {
    (void)in_sizes; (void)n_in; (void)out_size;
    const float* time_bar   = (const float*)d_in[0];
    const float* time_cur   = (const float*)d_in[1];
    const float* time_delta = (const float*)d_in[2];
    const int*   u          = (const int*)d_in[3];
    const int*   neighbors  = (const int*)d_in[4];
    const int*   neg_nodes  = (const int*)d_in[5];
    const float* z0         = (const float*)d_in[6];
    const float* W_omega    = (const float*)d_in[7];
    const float* b_omega    = (const float*)d_in[8];
    const float* W_h        = (const float*)d_in[9];
    const float* b_h        = (const float*)d_in[10];
    const float* W_e2n      = (const float*)d_in[11];
    const float* b_e2n      = (const float*)d_in[12];
    const float* W_rec_e    = (const float*)d_in[13];
    const float* b_rec_e    = (const float*)d_in[14];
    const float* W_rec_n    = (const float*)d_in[15];
    const float* b_rec_n    = (const float*)d_in[16];
    const float* W_time     = (const float*)d_in[17];
    const float* b_time     = (const float*)d_in[18];
    const float* w_t        = (const float*)d_in[19];
    const float* alpha      = (const float*)d_in[20];
    const float* psi        = (const float*)d_in[21];

    prep_kernel<<<Bb, TPB>>>(z0, u, neighbors, neg_nodes, W_h, W_e2n, W_rec_e,
                             W_rec_n, time_bar, time_cur, time_delta,
                             b_omega, w_t, alpha);
    conflict_kernel<<<(Bb * Tt + TPB - 1) / TPB, TPB>>>(u, neighbors, neg_nodes);
    levels_kernel<<<1, Bb>>>();
    dyrep_main<<<NCTA, TPB>>>(u, neighbors, neg_nodes, W_omega, b_h, b_e2n,
                              b_rec_e, b_rec_n, W_time, b_time, psi,
                              (float*)d_out);
}

// round 17
// speedup vs baseline: 20.0151x; 1.0393x over previous
#include <cuda_runtime.h>
#include <math.h>

#define Nn     100000
#define Hd     128
#define Bb     512
#define Dd     32
#define NEGS   5
#define Tt     38     // touches: u + 32 nb + 5 neg
#define Ww     33     // writes:  u + 32 nb
#define CSZ    5      // CTAs per cluster (= roles per step)
#define NCLUST 25
#define NCTA   125    // NCLUST * CSZ — co-residency proven at this size
#define TPB    256
#define HTSZ   65536

// ---------------- device scratch ----------------
__device__ float4 z_buf4[(size_t)Nn * 32];
#define z_buf ((float*)z_buf4)
__device__ float4 g_Wh4[4096], g_We2n4[4096], g_Wrece4[4096], g_Wrecn4[4096];
__device__ unsigned long long g_ht[HTSZ];
__device__ unsigned g_conf[Bb * 16];        // bitmatrix: row t2, bit t1 (t1<t2)
__device__ float g_prec[Bb * 64];           // per-step precomputed (layout below)
// per step t: [0..32] td positional; [33..37] hawkes add (neg); [38] hawkes add (u)
//   [39] en_mask (uint bits)  [40] en_u (uint 0/1)
__device__ int g_order[Bb];
__device__ int g_lvl_start[Bb + 1];
__device__ int g_nlv;
__device__ int g_done[Bb];                  // per-step completion counter (0..5)

__device__ __forceinline__ float sigmoidf_(float x) { return 1.0f / (1.0f + expf(-x)); }
__device__ __forceinline__ float softplusf_(float x) {
    return fmaxf(x, 0.0f) + log1pf(expf(-fabsf(x)));
}
__device__ __forceinline__ void ffma2(unsigned long long& d, unsigned long long a,
                                      unsigned long long b, unsigned long long c) {
    asm("fma.rn.f32x2 %0, %1, %2, %3;" : "=l"(d) : "l"(a), "l"(b), "l"(c));
}
__device__ __forceinline__ unsigned long long packf2(float v) {
    unsigned long long r;
    asm("mov.b64 %0, {%1, %1};" : "=l"(r) : "f"(v));
    return r;
}
#define CLUSTER_ARRIVE() asm volatile("barrier.cluster.arrive.aligned;" ::: "memory")
#define CLUSTER_WAIT()   asm volatile("barrier.cluster.wait.aligned;" ::: "memory")

// warp q of 4 covers k in [32q,32q+32) of out[i] = sum_k sv[k]*W[k*128+i]
__device__ __forceinline__ void matvec_part(const float4* __restrict__ W4,
                                            const float* __restrict__ sv,
                                            float* __restrict__ pb, int q, int lane) {
    float4 acc = make_float4(0.f, 0.f, 0.f, 0.f);
#pragma unroll
    for (int kk = 0; kk < 32; kk++) {
        int k = q * 32 + kk;
        float v = sv[k];
        float4 wv = W4[k * 32 + lane];
        acc.x = fmaf(v, wv.x, acc.x); acc.y = fmaf(v, wv.y, acc.y);
        acc.z = fmaf(v, wv.z, acc.z); acc.w = fmaf(v, wv.w, acc.w);
    }
    reinterpret_cast<float4*>(pb + q * 128)[lane] = acc;
}

// ---- 1: prep — clears, weight copies, z-row restore, per-step precompute ----
__global__ void prep_kernel(const float* __restrict__ z0,
                            const int* __restrict__ uu, const int* __restrict__ nbi,
                            const int* __restrict__ ngi,
                            const float* __restrict__ Wh, const float* __restrict__ We2n,
                            const float* __restrict__ Wrece, const float* __restrict__ Wrecn,
                            const float* __restrict__ tb, const float* __restrict__ tcur,
                            const float* __restrict__ tdelta,
                            const float* __restrict__ bomega,
                            const float* __restrict__ wt_, const float* __restrict__ alpha_) {
    __shared__ int nb_sh[Dd], su_sh;
    const int t = blockIdx.x, tid = threadIdx.x;
    const int lane = tid & 31;
    const int gidx = t * TPB + tid;

    if (gidx < HTSZ) g_ht[gidx] = 0ull;
    if (gidx < Bb * 16) g_conf[gidx] = 0u;
    if (gidx < Bb) g_done[gidx] = 0;

    if (gidx < Hd * Hd) {
        ((float*)g_Wh4)[gidx]    = __ldg(&Wh[gidx]);
        ((float*)g_We2n4)[gidx]  = __ldg(&We2n[gidx]);
        ((float*)g_Wrece4)[gidx] = __ldg(&Wrece[gidx]);
        ((float*)g_Wrecn4)[gidx] = __ldg(&Wrecn[gidx]);
    }

    const float tc    = __ldg(&tcur[t]);
    const float b_om  = __ldg(bomega);
    const float w_t   = __ldg(wt_);
    const float alpha = __ldg(alpha_);
    if (tid < Dd) nb_sh[tid] = __ldg(&nbi[t * Dd + tid]);
    else if (tid == Dd) su_sh = __ldg(&uu[t]);
    __syncthreads();
    if (tid < 33) {
        g_prec[t * 64 + tid] = tc - __ldg(&tb[(size_t)t * Nn + tid]);
    } else if (tid < 38) {
        int node = __ldg(&ngi[t * NEGS + tid - 33]);
        float tdn = tc - __ldg(&tb[(size_t)t * Nn + node]);
        g_prec[t * 64 + tid] = b_om + alpha * expf(-w_t * tdn);
    } else if (tid == 38) {
        float tsd = tc - __ldg(&tdelta[2 * t]);
        g_prec[t * 64 + 38] = b_om + alpha * expf(-w_t * tsd);
    }
    if (tid >= 64 && tid < 96) {  // warp 2: masks
        int j = tid - 64;
        int nbj = nb_sh[j], dup = 0;
        for (int j2 = j + 1; j2 < Dd; j2++) dup |= (nb_sh[j2] == nbj);
        unsigned bal  = __ballot_sync(0xffffffffu, !dup);
        unsigned balu = __ballot_sync(0xffffffffu, nbj == su_sh);
        if (j == 0) {
            g_prec[t * 64 + 39] = __uint_as_float(bal);
            g_prec[t * 64 + 40] = __uint_as_float(balu == 0 ? 1u : 0u);
        }
    }

    int gw = gidx >> 5;
    int nw = (gridDim.x * TPB) >> 5;
    for (int e = gw; e < Bb * Tt; e += nw) {
        int tt = e / Tt, i = e - tt * Tt;
        int node = (i == 0) ? __ldg(&uu[tt])
                 : (i < Ww) ? __ldg(&nbi[tt * Dd + i - 1])
                            : __ldg(&ngi[tt * NEGS + i - Ww]);
        const float* s = z0 + (size_t)node * Hd + lane * 4;
        float4 v;
        v.x = __ldg(s); v.y = __ldg(s + 1); v.z = __ldg(s + 2); v.w = __ldg(s + 3);
        z_buf4[(size_t)node * 32 + lane] = v;
    }
}

// ---- 2: conflicts via node hash table, O(B*Tt) ----
__global__ void conflict_kernel(const int* __restrict__ uu, const int* __restrict__ nbi,
                                const int* __restrict__ ngi) {
    int e = blockIdx.x * blockDim.x + threadIdx.x;
    if (e >= Bb * Tt) return;
    int step = e / Tt, i = e - step * Tt;
    int node = (i == 0) ? __ldg(&uu[step])
             : (i < Ww) ? __ldg(&nbi[step * Dd + i - 1])
                        : __ldg(&ngi[step * NEGS + i - Ww]);
    unsigned fl = (i < Ww) ? 1u : 0u;
    unsigned long long me = ((unsigned long long)node << 11)
                          | ((unsigned long long)step << 2) | (fl << 1) | 1ull;
    unsigned s = ((unsigned)node * 2654435761u) & (HTSZ - 1);
    for (;;) {
        unsigned long long old = atomicCAS(&g_ht[s], 0ull, me);
        if (old == 0ull) break;
        int onode = (int)(old >> 11);
        if (onode == node) {
            int ostep = (int)((old >> 2) & 511ull);
            unsigned ofl = (unsigned)((old >> 1) & 1ull);
            if (ostep != step && (fl | ofl)) {
                int t1 = min(step, ostep), t2 = max(step, ostep);
                atomicOr(&g_conf[t2 * 16 + (t1 >> 5)], 1u << (t1 & 31));
            }
        }
        s = (s + 1) & (HTSZ - 1);
    }
}

// ---- 3: exact longest-path levels, warp-serial chunks (NO spins) + sort ----
// g_order is level-sorted: every pred of a step appears strictly earlier.
__global__ void levels_kernel() {
    __shared__ unsigned lv[Bb];
    __shared__ unsigned cnt[Bb + 1];
    __shared__ unsigned maxl;
    const int t = threadIdx.x, lane = t & 31, ch = t >> 5;
    unsigned row[16];
#pragma unroll
    for (int j = 0; j < 16; j++) row[j] = g_conf[t * 16 + j];
    if (t == 0) maxl = 0;
    __syncthreads();
    unsigned mylvl = 0;
    for (int r = 0; r < 16; r++) {
        if (ch == r) {
            unsigned m = 0;
            for (int j = 0; j < r; j++) {
                unsigned wb = row[j];
                while (wb) {
                    int b = __ffs(wb) - 1; wb &= wb - 1;
                    unsigned l = lv[j * 32 + b];
                    if (l > m) m = l;
                }
            }
            unsigned inw = row[r];
            for (int p = 0; p < 32; p++) {
                if (lane == p) mylvl = m + 1u;
                unsigned v = __shfl_sync(0xffffffffu, mylvl, p);
                if (lane > p && ((inw >> p) & 1u) && v > m) m = v;
            }
            lv[t] = mylvl;
        }
        __syncthreads();
    }
    cnt[t] = 0;
    if (t == 0) cnt[Bb] = 0;
    __syncthreads();
    atomicAdd(&cnt[mylvl], 1u);
    atomicMax(&maxl, mylvl);
    __syncthreads();
    if (t == 0) {
        unsigned s = 0, M = maxl;
        for (unsigned l = 1; l <= M; l++) {
            unsigned c = cnt[l]; cnt[l] = s; g_lvl_start[l - 1] = (int)s; s += c;
        }
        g_lvl_start[M] = Bb;
        g_nlv = (int)M;
    }
    __syncthreads();
    g_order[atomicAdd(&cnt[mylvl], 1u)] = t;
}

// ---- 4: main — 1 cluster per step, per-step DATAFLOW; z-independent
//          prologue overlapped with the dependency spin ----
__global__ void __launch_bounds__(TPB, 1) __cluster_dims__(CSZ, 1, 1) dyrep_main(
    const int* __restrict__ uu, const int* __restrict__ nbi, const int* __restrict__ ngi,
    const float* __restrict__ Womega,
    const float* __restrict__ bh, const float* __restrict__ be2n,
    const float* __restrict__ brece, const float* __restrict__ brecn,
    const float* __restrict__ Wtime, const float* __restrict__ btime,
    const float* __restrict__ psi_, float* __restrict__ out)
{
    __shared__ int    nb_sh[Dd], su_s, neg_sh[NEGS];
    __shared__ float4 znb4[8][32];        // gemm: 8 nb rows | hub: 5 neg rows
    __shared__ float4 zu4[32];
    __shared__ ulonglong2 pbG[8][8][32];  // GEMM k-split partials [warp][row][lane]
    __shared__ float4 pbA4[4][32], pbB4[4][32];
    __shared__ float  m_part[2 * Hd];
    __shared__ float  mean_sh[Hd];
    __shared__ float  td_s[8];
    __shared__ unsigned en_s;
    __shared__ int    stg_node[8];
    __shared__ float4 stg_h4[8][32];      // raw GEMM results (phase2 -> phase3)
    __shared__ float  Wo_s[Hd], Wt_s[Hd], bt_s[Hd], brn_s[Hd], be2n_s[Hd], brece_s[Hd], bh_s[Hd];

    const int tid = threadIdx.x, wid = tid >> 5, lane = tid & 31, bid = blockIdx.x;
    const int cl = bid / CSZ, role = bid - cl * CSZ;
    const float psi = __ldg(psi_);

    if (tid < Hd) {
        Wo_s[tid] = __ldg(&Womega[tid]); Wt_s[tid] = __ldg(&Wtime[tid]);
        bt_s[tid] = __ldg(&btime[tid]);  brn_s[tid] = __ldg(&brecn[tid]);
        be2n_s[tid] = __ldg(&be2n[tid]); brece_s[tid] = __ldg(&brece[tid]);
        bh_s[tid] = __ldg(&bh[tid]);
    }
    __syncthreads();

    for (int i = cl; i < Bb; i += NCLUST) {
        const int t = g_order[i];
        const float* prec = &g_prec[t * 64];

        // ---- z-independent prologue part 1: indices ----
        if (tid < Dd)       nb_sh[tid] = __ldg(&nbi[t * Dd + tid]);
        else if (tid == Dd) su_s = __ldg(&uu[t]);
        else if (tid < Dd + 1 + NEGS) neg_sh[tid - 33] = __ldg(&ngi[t * NEGS + tid - 33]);
        __syncthreads();

        // ---- dependency spin (warp 0) OVERLAPPED with prec-derived loads ----
        if (tid < 32) {
#pragma unroll
            for (int j = 0; j < 16; j++) {
                unsigned wb = __ldcg(&g_conf[t * 16 + j]);
                if ((wb >> lane) & 1u) {
                    int p = j * 32 + lane;
                    while (*(volatile int*)&g_done[p] != CSZ) {}
                }
            }
            __threadfence();
        } else if (role < 4) {
            const int j0 = role * 8;
            if (tid < 40) {
                td_s[tid - 32] = __ldcg(&prec[1 + j0 + tid - 32]);
                stg_node[tid - 32] = nb_sh[j0 + tid - 32];
            } else if (tid == 40) {
                en_s = (__float_as_uint(__ldcg(&prec[39])) >> j0) & 0xffu;
            }
        } else {
            if (tid == 32)      td_s[0] = __ldcg(&prec[0]);
            else if (tid == 33) en_s = __float_as_uint(__ldcg(&prec[40]));
        }
        __syncthreads();   // preds' writes visible (warp0 fence) + derived smem ready

        if (role < 4) {
            // ===== GEMM role: rows [8*role, 8*role+8), k-split =====
            const int j0 = role * 8;
            znb4[wid][lane] = __ldcg(&z_buf4[(size_t)nb_sh[j0 + wid] * 32 + lane]);
            if (tid < 32) zu4[tid] = __ldcg(&z_buf4[(size_t)su_s * 32 + tid]);
            __syncthreads();        // all pre-update reads captured in smem
            CLUSTER_ARRIVE();       // signal: my reads done

            // phase 1: rank-1 k-split GEMM; W_rec_n read ONCE per CTA
            {
                const float* zsh = (const float*)znb4;
                const ulonglong2* W2 = reinterpret_cast<const ulonglong2*>(g_Wrecn4);
                unsigned long long a01[8], a23[8];
#pragma unroll
                for (int r = 0; r < 8; r++) { a01[r] = 0ull; a23[r] = 0ull; }
                const int kb = wid * 16;
#pragma unroll
                for (int kk = 0; kk < 16; kk++) {
                    const int kx = kb + kk;
                    ulonglong2 wv = W2[kx * 32 + lane];
#pragma unroll
                    for (int r = 0; r < 8; r++) {
                        unsigned long long zz = packf2(zsh[r * Hd + kx]);
                        ffma2(a01[r], zz, wv.x, a01[r]);
                        ffma2(a23[r], zz, wv.y, a23[r]);
                    }
                }
#pragma unroll
                for (int r = 0; r < 8; r++) {
                    pbG[wid][r][lane].x = a01[r];
                    pbG[wid][r][lane].y = a23[r];
                }
            }
            __syncthreads();

            // phase 2: warps 0-3 matvec s=z_u@We2n; warps 4-7 reduce partials
            if (wid < 4) {
                matvec_part(g_We2n4, (const float*)zu4, (float*)pbA4, wid, lane);
            } else {
                const int sbase = (tid - 128) * 2;
#pragma unroll
                for (int ss = 0; ss < 2; ss++) {
                    const int slot = sbase + ss;
                    const int r = slot >> 5, ln = slot & 31;
                    float4 acc = make_float4(0.f, 0.f, 0.f, 0.f);
#pragma unroll
                    for (int w2 = 0; w2 < 8; w2++) {
                        float4 v = *reinterpret_cast<const float4*>(&pbG[w2][r][ln]);
                        acc.x += v.x; acc.y += v.y; acc.z += v.z; acc.w += v.w;
                    }
                    stg_h4[r][ln] = acc;
                }
            }
            __syncthreads();

            // phase 3: combine into registers (flush mapping = compute mapping)
            const int c0 = lane * 4;
            const float* pa = (const float*)pbA4;
            const float4 g4 = stg_h4[wid][lane];
            const float td = td_s[wid];
            float4 h;
            h.x = sigmoidf_(g4.x + pa[c0]     + pa[128 + c0]     + pa[256 + c0]     + pa[384 + c0]
                            + be2n_s[c0]     + brn_s[c0]     + bt_s[c0]     + td * Wt_s[c0]);
            h.y = sigmoidf_(g4.y + pa[c0 + 1] + pa[128 + c0 + 1] + pa[256 + c0 + 1] + pa[384 + c0 + 1]
                            + be2n_s[c0 + 1] + brn_s[c0 + 1] + bt_s[c0 + 1] + td * Wt_s[c0 + 1]);
            h.z = sigmoidf_(g4.z + pa[c0 + 2] + pa[128 + c0 + 2] + pa[256 + c0 + 2] + pa[384 + c0 + 2]
                            + be2n_s[c0 + 2] + brn_s[c0 + 2] + bt_s[c0 + 2] + td * Wt_s[c0 + 2]);
            h.w = sigmoidf_(g4.w + pa[c0 + 3] + pa[128 + c0 + 3] + pa[256 + c0 + 3] + pa[384 + c0 + 3]
                            + be2n_s[c0 + 3] + brn_s[c0 + 3] + bt_s[c0 + 3] + td * Wt_s[c0 + 3]);
            const int node_r = stg_node[wid];     // snapshot before next-iter smem reuse
            const unsigned en_r = en_s;

            CLUSTER_WAIT();         // all 5 roles' reads done -> safe to write
            if ((en_r >> wid) & 1u)
                z_buf4[(size_t)node_r * 32 + lane] = h;
        } else {
            // ===== hub role: mean, W_h, W_rec_e, h_u, hawkes =====
            if (wid < NEGS)    znb4[wid][lane] = __ldcg(&z_buf4[(size_t)neg_sh[wid] * 32 + lane]);
            else if (wid == 5) zu4[lane] = __ldcg(&z_buf4[(size_t)su_s * 32 + lane]);
            {   // mean accumulate (pre-update reads)
                const int i2 = tid & 127, r0 = (tid >> 7) * 16;
                float a = 0.f;
#pragma unroll
                for (int r = 0; r < 16; r++)
                    a += __ldcg(&z_buf[(size_t)nb_sh[r0 + r] * Hd + i2]);
                m_part[tid] = a;
            }
            __syncthreads();        // all pre-update reads captured
            CLUSTER_ARRIVE();

            const int su_r = su_s;          // snapshots (smem reused next iter)
            if (tid < Hd) mean_sh[tid] = (m_part[tid] + m_part[Hd + tid]) * (1.0f / 32.0f);
            __syncthreads();
            const unsigned en_r = en_s;
            if (wid < 4) matvec_part(g_Wrece4, (const float*)zu4, (float*)pbA4, wid, lane);
            else         matvec_part(g_Wh4, mean_sh, (float*)pbB4, wid - 4, lane);
            __syncthreads();
            float hval = 0.f;
            if (tid < Hd) {
                const float* pa = (const float*)pbA4;
                const float* pb = (const float*)pbB4;
                float hh = pa[tid] + pa[Hd + tid] + pa[2 * Hd + tid] + pa[3 * Hd + tid] + brece_s[tid]
                         + pb[tid] + pb[Hd + tid] + pb[2 * Hd + tid] + pb[3 * Hd + tid] + bh_s[tid]
                         + td_s[0] * Wt_s[tid] + bt_s[tid];
                hval = sigmoidf_(hh);
            }
            if (wid < 6) {   // hawkes on pre-update embeddings (in smem)
                const float* rowp = (wid < NEGS) ? (const float*)znb4[wid] : (const float*)zu4;
                float a = 0.f;
#pragma unroll
                for (int c = 0; c < 4; c++) {
                    int i2 = lane + 32 * c;
                    a = fmaf(rowp[i2], Wo_s[i2], a);
                }
#pragma unroll
                for (int o = 16; o > 0; o >>= 1) a += __shfl_down_sync(0xffffffffu, a, o);
                if (lane == 0) {
                    float hb = __ldcg(&prec[(wid == 5) ? 38 : (33 + wid)]);
                    float lamv = psi * softplusf_((a + hb) / psi);
                    if (wid == 5) out[t] = lamv;
                    else          out[Bb + t * NEGS + wid] = lamv * (1.0f / NEGS);
                }
            }

            CLUSTER_WAIT();
            if (en_r && tid < Hd)
                z_buf[(size_t)su_r * Hd + tid] = hval;
        }

        // ---- signal: this role's writes are globally visible ----
        __syncthreads();                     // all warps' stores ordered before fence
        if (tid == 0) {
            __threadfence();                 // cumulative: publishes whole CTA's writes
            atomicAdd(&g_done[t], 1);
        }
    }
}

// ---------------- launch ----------------
extern "C" void kernel_launch(void* const* d_in, const int* in_sizes, int n_in,
                              void* d_out, int out_size) {
    (void)in_sizes; (void)n_in; (void)out_size;
    const float* time_bar   = (const float*)d_in[0];
    const float* time_cur   = (const float*)d_in[1];
    const float* time_delta = (const float*)d_in[2];
    const int*   u          = (const int*)d_in[3];
    const int*   neighbors  = (const int*)d_in[4];
    const int*   neg_nodes  = (const int*)d_in[5];
    const float* z0         = (const float*)d_in[6];
    const float* W_omega    = (const float*)d_in[7];
    const float* b_omega    = (const float*)d_in[8];
    const float* W_h        = (const float*)d_in[9];
    const float* b_h        = (const float*)d_in[10];
    const float* W_e2n      = (const float*)d_in[11];
    const float* b_e2n      = (const float*)d_in[12];
    const float* W_rec_e    = (const float*)d_in[13];
    const float* b_rec_e    = (const float*)d_in[14];
    const float* W_rec_n    = (const float*)d_in[15];
    const float* b_rec_n    = (const float*)d_in[16];
    const float* W_time     = (const float*)d_in[17];
    const float* b_time     = (const float*)d_in[18];
    const float* w_t        = (const float*)d_in[19];
    const float* alpha      = (const float*)d_in[20];
    const float* psi        = (const float*)d_in[21];

    prep_kernel<<<Bb, TPB>>>(z0, u, neighbors, neg_nodes, W_h, W_e2n, W_rec_e,
                             W_rec_n, time_bar, time_cur, time_delta,
                             b_omega, w_t, alpha);
    conflict_kernel<<<(Bb * Tt + TPB - 1) / TPB, TPB>>>(u, neighbors, neg_nodes);
    levels_kernel<<<1, Bb>>>();
    dyrep_main<<<NCTA, TPB>>>(u, neighbors, neg_nodes, W_omega, b_h, b_e2n,
                              b_rec_e, b_rec_n, W_time, b_time, psi,
                              (float*)d_out);
}